// round 2
// baseline (speedup 1.0000x reference)
#include <cuda_runtime.h>
#include <cuda_bf16.h>
#include <math.h>

// Problem constants
#define BB   2
#define TT   2048
#define HH   1024
#define NH   16
#define HD   64
#define MM   (BB*TT)        // 4096
#define NGRP 32
#define GSZ  (HH/NGRP)      // 32 channels per group
#define GELEM (TT*GSZ)      // 65536 elements per (batch, group)

// Scratch (device globals; no allocation allowed)
__device__ float g_xn[MM*HH];        // normalized activations (reused)
__device__ float g_q [MM*HH];        // q in [B,nh,T,hd]
__device__ float g_a [MM*HH];        // attention output [B,T,H]
__device__ float g_x1[MM*HH];        // residual stream after attention
__device__ float g_h [MM*4*HH];      // MLP hidden [4096,4096]

// ---------------------------------------------------------------------------
// GroupNorm: mean/var over (T, channels_in_group) per (batch, group)
// ---------------------------------------------------------------------------
__global__ void groupnorm_kernel(const float* __restrict__ x,
                                 const float* __restrict__ w,
                                 const float* __restrict__ b,
                                 float* __restrict__ y)
{
    int bg = blockIdx.x;
    int batch = bg >> 5;
    int g = bg & 31;
    const float* xp = x + (size_t)batch * TT * HH + g * GSZ;
    float* yp       = y + (size_t)batch * TT * HH + g * GSZ;

    float s = 0.f, ss = 0.f;
    for (int idx = threadIdx.x; idx < GELEM; idx += 256) {
        int t = idx >> 5, c = idx & 31;
        float v = xp[(size_t)t * HH + c];
        s += v; ss += v * v;
    }
    __shared__ float rs[256], rss[256];
    rs[threadIdx.x] = s; rss[threadIdx.x] = ss;
    __syncthreads();
    for (int o = 128; o > 0; o >>= 1) {
        if (threadIdx.x < o) {
            rs[threadIdx.x]  += rs[threadIdx.x + o];
            rss[threadIdx.x] += rss[threadIdx.x + o];
        }
        __syncthreads();
    }
    __shared__ float s_mean, s_rstd;
    if (threadIdx.x == 0) {
        float mean = rs[0] * (1.0f / GELEM);
        float var  = rss[0] * (1.0f / GELEM) - mean * mean;
        s_mean = mean;
        s_rstd = rsqrtf(var + 1e-5f);
    }
    __syncthreads();
    float mean = s_mean, rstd = s_rstd;
    for (int idx = threadIdx.x; idx < GELEM; idx += 256) {
        int t = idx >> 5, c = idx & 31;
        int ch = g * GSZ + c;
        float v = xp[(size_t)t * HH + c];
        yp[(size_t)t * HH + c] = (v - mean) * rstd * w[ch] + b[ch];
    }
}

// ---------------------------------------------------------------------------
// SGEMM: C = A[M,K] @ B[K,N] + bias, with epilogue modes:
//   MODE 0: QKV scatter  (C=q [B,nh,T,hd], C2=present_k, C3=present_v)
//   MODE 1: + residual   (C = val + res[m,n])
//   MODE 2: GELU         (C = gelu(val))
// BM=BN=128, BK=16, 256 threads, 8x8 per-thread microtile.
// All dims divisible by tiles (no guards).
// ---------------------------------------------------------------------------
#define GBM 128
#define GBN 128
#define GBK 16

__device__ __forceinline__ float gelu_f(float v) {
    const float c = 0.7978845608028654f;   // sqrt(2/pi)
    float u = c * (v + 0.044715f * v * v * v);
    return 0.5f * v * (1.0f + tanhf(u));
}

template<int MODE>
__global__ void __launch_bounds__(256, 2)
sgemm_kernel(const float* __restrict__ A, const float* __restrict__ Bm,
             const float* __restrict__ bias, const float* __restrict__ res,
             float* __restrict__ C, float* __restrict__ C2, float* __restrict__ C3,
             int M, int N, int K)
{
    __shared__ float As[GBK][GBM];
    __shared__ float Bs[GBK][GBN];

    int tid = threadIdx.x;
    int tx = tid & 15, ty = tid >> 4;
    int bm = blockIdx.y * GBM, bn = blockIdx.x * GBN;

    float acc[8][8];
    #pragma unroll
    for (int i = 0; i < 8; i++)
        #pragma unroll
        for (int j = 0; j < 8; j++) acc[i][j] = 0.f;

    const float* Aptr = A + (size_t)bm * K;
    const float* Bptr = Bm + bn;

    for (int k0 = 0; k0 < K; k0 += GBK) {
        // A tile: 128x16 -> transposed into As[K][M]
        #pragma unroll
        for (int i = 0; i < 2; i++) {
            int f4 = tid + i * 256;
            int ar = f4 >> 2;           // 0..127
            int ac = (f4 & 3) * 4;      // 0,4,8,12
            float4 v = *(const float4*)(Aptr + (size_t)ar * K + k0 + ac);
            As[ac + 0][ar] = v.x;
            As[ac + 1][ar] = v.y;
            As[ac + 2][ar] = v.z;
            As[ac + 3][ar] = v.w;
        }
        // B tile: 16x128 direct
        #pragma unroll
        for (int i = 0; i < 2; i++) {
            int f4 = tid + i * 256;
            int br = f4 >> 5;           // 0..15
            int bc = (f4 & 31) * 4;     // 0..124
            *(float4*)(&Bs[br][bc]) = *(const float4*)(Bptr + (size_t)(k0 + br) * N + bc);
        }
        __syncthreads();
        #pragma unroll
        for (int k = 0; k < GBK; k++) {
            float a[8], bb[8];
            #pragma unroll
            for (int i = 0; i < 8; i++) a[i]  = As[k][ty * 8 + i];
            #pragma unroll
            for (int j = 0; j < 8; j++) bb[j] = Bs[k][tx * 8 + j];
            #pragma unroll
            for (int i = 0; i < 8; i++)
                #pragma unroll
                for (int j = 0; j < 8; j++)
                    acc[i][j] = fmaf(a[i], bb[j], acc[i][j]);
        }
        __syncthreads();
    }

    int m0 = bm + ty * 8;
    int n0 = bn + tx * 8;
    #pragma unroll
    for (int i = 0; i < 8; i++) {
        int m = m0 + i;
        #pragma unroll
        for (int j = 0; j < 8; j++) {
            int n = n0 + j;
            float val = acc[i][j] + bias[n];
            if (MODE == 0) {
                int bidx = m >> 11, t = m & 2047;
                int part = n >> 10;       // 0=q 1=k 2=v
                int nn = n & 1023;
                int h = nn >> 6, d = nn & 63;
                size_t idx = ((((size_t)bidx * NH + h) * TT) + t) * HD + d;
                if (part == 0)      C [idx] = val;
                else if (part == 1) C2[idx] = val;
                else                C3[idx] = val;
            } else if (MODE == 1) {
                size_t idx = (size_t)m * N + n;
                C[idx] = val + res[idx];
            } else {
                C[(size_t)m * N + n] = gelu_f(val);
            }
        }
    }
}

// ---------------------------------------------------------------------------
// Flash attention (fp32, no scale, causal). 64x64 tiles, hd=64.
// grid: (T/64, B*nh). 256 threads: 16x16, each owns a 4x4 S microtile
// and a 4(rows)x4(dims) O microtile.
// ---------------------------------------------------------------------------
#define BQ 64
#define SSTR 65

__global__ void __launch_bounds__(256, 3)
flash_kernel(const float* __restrict__ Q, const float* __restrict__ Kp,
             const float* __restrict__ Vp, float* __restrict__ Aout)
{
    extern __shared__ float sh[];
    float* Qs = sh;                  // 64 x 65
    float* Ks = Qs + 64 * SSTR;
    float* Vs = Ks + 64 * SSTR;
    float* Ps = Vs + 64 * SSTR;

    int qb = blockIdx.x;             // q tile 0..31
    int bh = blockIdx.y;             // b*16+h, 0..31
    int tid = threadIdx.x;
    int tc = tid & 15, tr = tid >> 4;
    int r0 = tr * 4;                 // rows within tile
    int c0 = tc * 4;                 // cols / dims within tile

    const float* qbase = Q  + ((size_t)bh * TT + (size_t)qb * BQ) * HD;
    const float* kbase = Kp + (size_t)bh * TT * HD;
    const float* vbase = Vp + (size_t)bh * TT * HD;

    for (int idx = tid; idx < BQ * HD; idx += 256)
        Qs[(idx >> 6) * SSTR + (idx & 63)] = qbase[idx];

    float m_i[4], l_i[4], O[4][4];
    #pragma unroll
    for (int i = 0; i < 4; i++) {
        m_i[i] = -1e30f; l_i[i] = 0.f;
        #pragma unroll
        for (int d = 0; d < 4; d++) O[i][d] = 0.f;
    }

    int ntiles = qb + 1;
    for (int kt = 0; kt < ntiles; kt++) {
        __syncthreads();   // protect Ks/Vs/Ps from previous iteration readers
        for (int idx = tid; idx < BQ * HD; idx += 256) {
            int rr = idx >> 6, cc = idx & 63;
            Ks[rr * SSTR + cc] = kbase[(size_t)kt * BQ * HD + idx];
            Vs[rr * SSTR + cc] = vbase[(size_t)kt * BQ * HD + idx];
        }
        __syncthreads();

        // S = Q @ K^T (4x4 per thread)
        float s[4][4];
        #pragma unroll
        for (int i = 0; i < 4; i++)
            #pragma unroll
            for (int j = 0; j < 4; j++) s[i][j] = 0.f;

        #pragma unroll 8
        for (int k = 0; k < HD; k++) {
            float a[4], bbr[4];
            #pragma unroll
            for (int i = 0; i < 4; i++) a[i]   = Qs[(r0 + i) * SSTR + k];
            #pragma unroll
            for (int j = 0; j < 4; j++) bbr[j] = Ks[(c0 + j) * SSTR + k];
            #pragma unroll
            for (int i = 0; i < 4; i++)
                #pragma unroll
                for (int j = 0; j < 4; j++)
                    s[i][j] = fmaf(a[i], bbr[j], s[i][j]);
        }

        if (kt == qb) {  // diagonal tile: mask col > row (within-tile indices)
            #pragma unroll
            for (int i = 0; i < 4; i++)
                #pragma unroll
                for (int j = 0; j < 4; j++)
                    if (c0 + j > r0 + i) s[i][j] = -1e30f;
        }

        // online softmax per row; 16 threads (tc) share a row
        #pragma unroll
        for (int i = 0; i < 4; i++) {
            float mx = s[i][0];
            #pragma unroll
            for (int j = 1; j < 4; j++) mx = fmaxf(mx, s[i][j]);
            mx = fmaxf(mx, __shfl_xor_sync(0xffffffffu, mx, 1));
            mx = fmaxf(mx, __shfl_xor_sync(0xffffffffu, mx, 2));
            mx = fmaxf(mx, __shfl_xor_sync(0xffffffffu, mx, 4));
            mx = fmaxf(mx, __shfl_xor_sync(0xffffffffu, mx, 8));
            float m_new = fmaxf(m_i[i], mx);
            float sum = 0.f;
            #pragma unroll
            for (int j = 0; j < 4; j++) {
                s[i][j] = __expf(s[i][j] - m_new);
                sum += s[i][j];
            }
            sum += __shfl_xor_sync(0xffffffffu, sum, 1);
            sum += __shfl_xor_sync(0xffffffffu, sum, 2);
            sum += __shfl_xor_sync(0xffffffffu, sum, 4);
            sum += __shfl_xor_sync(0xffffffffu, sum, 8);
            float alpha = __expf(m_i[i] - m_new);
            l_i[i] = l_i[i] * alpha + sum;
            m_i[i] = m_new;
            #pragma unroll
            for (int d = 0; d < 4; d++) O[i][d] *= alpha;
            // stash P
            #pragma unroll
            for (int j = 0; j < 4; j++)
                Ps[(r0 + i) * SSTR + c0 + j] = s[i][j];
        }
        __syncthreads();

        // O += P @ V
        #pragma unroll 8
        for (int j = 0; j < BQ; j++) {
            float p[4], v[4];
            #pragma unroll
            for (int i = 0; i < 4; i++) p[i] = Ps[(r0 + i) * SSTR + j];
            #pragma unroll
            for (int d = 0; d < 4; d++) v[d] = Vs[j * SSTR + c0 + d];
            #pragma unroll
            for (int i = 0; i < 4; i++)
                #pragma unroll
                for (int d = 0; d < 4; d++)
                    O[i][d] = fmaf(p[i], v[d], O[i][d]);
        }
    }

    // write out: a[b, t, h*64 + d]
    int batch = bh >> 4, h = bh & 15;
    #pragma unroll
    for (int i = 0; i < 4; i++) {
        int t = qb * BQ + r0 + i;
        float inv = 1.0f / l_i[i];
        float4 o4 = make_float4(O[i][0] * inv, O[i][1] * inv, O[i][2] * inv, O[i][3] * inv);
        *(float4*)(Aout + ((size_t)batch * TT + t) * HH + h * HD + c0) = o4;
    }
}

// ---------------------------------------------------------------------------
// Launch
// ---------------------------------------------------------------------------
extern "C" void kernel_launch(void* const* d_in, const int* in_sizes, int n_in,
                              void* d_out, int out_size)
{
    const float* x       = (const float*)d_in[0];
    const float* w_attn  = (const float*)d_in[1];
    const float* b_attn  = (const float*)d_in[2];
    const float* w_aproj = (const float*)d_in[3];
    const float* b_aproj = (const float*)d_in[4];
    const float* ln1_w   = (const float*)d_in[5];
    const float* ln1_b   = (const float*)d_in[6];
    const float* ln2_w   = (const float*)d_in[7];
    const float* ln2_b   = (const float*)d_in[8];
    const float* w_fc    = (const float*)d_in[9];
    const float* b_fc    = (const float*)d_in[10];
    const float* w_mproj = (const float*)d_in[11];
    const float* b_mproj = (const float*)d_in[12];

    float* out_x = (float*)d_out;
    float* pk = out_x + (size_t)MM * HH;          // present[0] = k [B,nh,T,hd]
    float* pv = pk + (size_t)MM * HH;             // present[1] = v

    float *xn, *q, *a, *x1, *h;
    cudaGetSymbolAddress((void**)&xn, g_xn);
    cudaGetSymbolAddress((void**)&q,  g_q);
    cudaGetSymbolAddress((void**)&a,  g_a);
    cudaGetSymbolAddress((void**)&x1, g_x1);
    cudaGetSymbolAddress((void**)&h,  g_h);

    // 1. groupnorm(x) -> xn
    groupnorm_kernel<<<BB * NGRP, 256>>>(x, ln1_w, ln1_b, xn);

    // 2. qkv = xn @ w_attn + b_attn; scatter q -> [B,nh,T,hd], k/v -> present
    sgemm_kernel<0><<<dim3(3 * HH / GBN, MM / GBM), 256>>>(
        xn, w_attn, b_attn, nullptr, q, pk, pv, MM, 3 * HH, HH);

    // 3. flash attention -> a [B,T,H]
    size_t shmem = 4 * 64 * SSTR * sizeof(float);
    cudaFuncSetAttribute(flash_kernel, cudaFuncAttributeMaxDynamicSharedMemorySize, (int)shmem);
    flash_kernel<<<dim3(TT / BQ, BB * NH), 256, shmem>>>(q, pk, pv, a);

    // 4. x1 = a @ w_aproj + b_aproj + x
    sgemm_kernel<1><<<dim3(HH / GBN, MM / GBM), 256>>>(
        a, w_aproj, b_aproj, x, x1, nullptr, nullptr, MM, HH, HH);

    // 5. groupnorm(x1) -> xn
    groupnorm_kernel<<<BB * NGRP, 256>>>(x1, ln2_w, ln2_b, xn);

    // 6. h = gelu(xn @ w_fc + b_fc)
    sgemm_kernel<2><<<dim3(4 * HH / GBN, MM / GBM), 256>>>(
        xn, w_fc, b_fc, nullptr, h, nullptr, nullptr, MM, 4 * HH, HH);

    // 7. out_x = h @ w_mproj + b_mproj + x1
    sgemm_kernel<1><<<dim3(HH / GBN, MM / GBM), 256>>>(
        h, w_mproj, b_mproj, x1, out_x, nullptr, nullptr, MM, HH, 4 * HH);
}

// round 3
// speedup vs baseline: 1.6105x; 1.6105x over previous
#include <cuda_runtime.h>
#include <cuda_bf16.h>
#include <math.h>

// Problem constants
#define BB   2
#define TT   2048
#define HH   1024
#define NH   16
#define HD   64
#define MM   (BB*TT)        // 4096
#define NGRP 32
#define GSZ  (HH/NGRP)      // 32
#define GELEM (TT*GSZ)      // 65536

// Scratch (device globals; no allocation allowed)
__device__ float g_xn[MM*HH];
__device__ float g_q [MM*HH];
__device__ float g_a [MM*HH];
__device__ float g_x1[MM*HH];
__device__ float g_h [MM*4*HH];

// ---------------------------------------------------------------------------
// GroupNorm
// ---------------------------------------------------------------------------
__global__ void groupnorm_kernel(const float* __restrict__ x,
                                 const float* __restrict__ w,
                                 const float* __restrict__ b,
                                 float* __restrict__ y)
{
    int bg = blockIdx.x;
    int batch = bg >> 5;
    int g = bg & 31;
    const float* xp = x + (size_t)batch * TT * HH + g * GSZ;
    float* yp       = y + (size_t)batch * TT * HH + g * GSZ;

    float s = 0.f, ss = 0.f;
    for (int idx = threadIdx.x; idx < GELEM; idx += 256) {
        int t = idx >> 5, c = idx & 31;
        float v = xp[(size_t)t * HH + c];
        s += v; ss += v * v;
    }
    __shared__ float rs[256], rss[256];
    rs[threadIdx.x] = s; rss[threadIdx.x] = ss;
    __syncthreads();
    for (int o = 128; o > 0; o >>= 1) {
        if (threadIdx.x < o) {
            rs[threadIdx.x]  += rs[threadIdx.x + o];
            rss[threadIdx.x] += rss[threadIdx.x + o];
        }
        __syncthreads();
    }
    __shared__ float s_mean, s_rstd;
    if (threadIdx.x == 0) {
        float mean = rs[0] * (1.0f / GELEM);
        float var  = rss[0] * (1.0f / GELEM) - mean * mean;
        s_mean = mean;
        s_rstd = rsqrtf(var + 1e-5f);
    }
    __syncthreads();
    float mean = s_mean, rstd = s_rstd;
    for (int idx = threadIdx.x; idx < GELEM; idx += 256) {
        int t = idx >> 5, c = idx & 31;
        int ch = g * GSZ + c;
        float v = xp[(size_t)t * HH + c];
        yp[(size_t)t * HH + c] = (v - mean) * rstd * w[ch] + b[ch];
    }
}

// ---------------------------------------------------------------------------
// TF32 tensor-core GEMM via mma.sync.m16n8k8
//   C = A[M,K] @ B[K,N] + bias, epilogue MODE as before
// BM=BN=128, BK=32, 256 threads (8 warps), warp tile 64x32.
// ---------------------------------------------------------------------------
#define GBM 128
#define GBN 128
#define GBK 32
#define SPAD 136   // smem row stride: 136 mod 32 = 8 banks -> conflict-free frags

__device__ __forceinline__ float gelu_f(float v) {
    const float c = 0.7978845608028654f;
    float u = c * (v + 0.044715f * v * v * v);
    return 0.5f * v * (1.0f + tanhf(u));
}

__device__ __forceinline__ unsigned f2tf(float x) {
    unsigned u;
    asm("cvt.rna.tf32.f32 %0, %1;" : "=r"(u) : "f"(x));
    return u;
}

__device__ __forceinline__ void mma_tf32(float* d, const unsigned* a, const unsigned* b) {
    asm volatile(
        "mma.sync.aligned.m16n8k8.row.col.f32.tf32.tf32.f32 "
        "{%0,%1,%2,%3}, {%4,%5,%6,%7}, {%8,%9}, {%0,%1,%2,%3};"
        : "+f"(d[0]), "+f"(d[1]), "+f"(d[2]), "+f"(d[3])
        : "r"(a[0]), "r"(a[1]), "r"(a[2]), "r"(a[3]),
          "r"(b[0]), "r"(b[1]));
}

template<int MODE>
__global__ void __launch_bounds__(256)
tgemm_kernel(const float* __restrict__ A, const float* __restrict__ Bm,
             const float* __restrict__ bias, const float* __restrict__ res,
             float* __restrict__ C, float* __restrict__ C2, float* __restrict__ C3,
             int M, int N, int K)
{
    __shared__ float As[GBK][SPAD];
    __shared__ float Bs[GBK][SPAD];

    int tid  = threadIdx.x;
    int wid  = tid >> 5;
    int lane = tid & 31;
    int wm = wid >> 2;          // 0..1
    int wn = wid & 3;           // 0..3
    int lr = lane >> 2;         // 0..7
    int lc = lane & 3;          // 0..3

    int bm = blockIdx.y * GBM, bn = blockIdx.x * GBN;

    float acc[4][4][4];
    #pragma unroll
    for (int i = 0; i < 4; i++)
        #pragma unroll
        for (int j = 0; j < 4; j++)
            #pragma unroll
            for (int e = 0; e < 4; e++) acc[i][j][e] = 0.f;

    const float* Aptr = A + (size_t)bm * K;
    const float* Bptr = Bm + bn;

    for (int k0 = 0; k0 < K; k0 += GBK) {
        // A tile: 128 x 32, transposed into As[k][m], tf32-rounded
        #pragma unroll
        for (int i = 0; i < 4; i++) {
            int f4 = tid + i * 256;
            int ar = f4 >> 3;            // 0..127
            int ac = (f4 & 7) * 4;       // 0..28
            float4 v = *(const float4*)(Aptr + (size_t)ar * K + k0 + ac);
            As[ac + 0][ar] = __uint_as_float(f2tf(v.x));
            As[ac + 1][ar] = __uint_as_float(f2tf(v.y));
            As[ac + 2][ar] = __uint_as_float(f2tf(v.z));
            As[ac + 3][ar] = __uint_as_float(f2tf(v.w));
        }
        // B tile: 32 x 128, Bs[k][n], tf32-rounded
        #pragma unroll
        for (int i = 0; i < 4; i++) {
            int f4 = tid + i * 256;
            int br = f4 >> 5;            // 0..31
            int bc = (f4 & 31) * 4;      // 0..124
            float4 v = *(const float4*)(Bptr + (size_t)(k0 + br) * N + bc);
            Bs[br][bc + 0] = __uint_as_float(f2tf(v.x));
            Bs[br][bc + 1] = __uint_as_float(f2tf(v.y));
            Bs[br][bc + 2] = __uint_as_float(f2tf(v.z));
            Bs[br][bc + 3] = __uint_as_float(f2tf(v.w));
        }
        __syncthreads();

        #pragma unroll
        for (int kk = 0; kk < GBK / 8; kk++) {
            int kb = kk * 8;
            unsigned af[4][4], bf[4][2];
            #pragma unroll
            for (int i = 0; i < 4; i++) {
                int m0 = wm * 64 + i * 16 + lr;
                af[i][0] = __float_as_uint(As[kb + lc    ][m0    ]);
                af[i][1] = __float_as_uint(As[kb + lc    ][m0 + 8]);
                af[i][2] = __float_as_uint(As[kb + lc + 4][m0    ]);
                af[i][3] = __float_as_uint(As[kb + lc + 4][m0 + 8]);
            }
            #pragma unroll
            for (int j = 0; j < 4; j++) {
                int n0 = wn * 32 + j * 8 + lr;
                bf[j][0] = __float_as_uint(Bs[kb + lc    ][n0]);
                bf[j][1] = __float_as_uint(Bs[kb + lc + 4][n0]);
            }
            #pragma unroll
            for (int i = 0; i < 4; i++)
                #pragma unroll
                for (int j = 0; j < 4; j++)
                    mma_tf32(acc[i][j], af[i], bf[j]);
        }
        __syncthreads();
    }

    // Epilogue. c0:(r,c) c1:(r,c+1) c2:(r+8,c) c3:(r+8,c+1)
    #pragma unroll
    for (int i = 0; i < 4; i++) {
        int rbase = bm + wm * 64 + i * 16 + lr;
        #pragma unroll
        for (int j = 0; j < 4; j++) {
            int cbase = bn + wn * 32 + j * 8 + 2 * lc;
            #pragma unroll
            for (int e = 0; e < 4; e++) {
                int m = rbase + (e >> 1) * 8;
                int n = cbase + (e & 1);
                float val = acc[i][j][e] + bias[n];
                if (MODE == 0) {
                    int bidx = m >> 11, t = m & 2047;
                    int part = n >> 10;
                    int nn = n & 1023;
                    int h = nn >> 6, d = nn & 63;
                    size_t idx = ((((size_t)bidx * NH + h) * TT) + t) * HD + d;
                    if (part == 0)      C [idx] = val;
                    else if (part == 1) C2[idx] = val;
                    else                C3[idx] = val;
                } else if (MODE == 1) {
                    size_t idx = (size_t)m * N + n;
                    C[idx] = val + res[idx];
                } else {
                    C[(size_t)m * N + n] = gelu_f(val);
                }
            }
        }
    }
}

// ---------------------------------------------------------------------------
// Flash attention (fp32, no scale, causal). Unchanged from R1.
// ---------------------------------------------------------------------------
#define BQ 64
#define SSTR 65

__global__ void __launch_bounds__(256, 3)
flash_kernel(const float* __restrict__ Q, const float* __restrict__ Kp,
             const float* __restrict__ Vp, float* __restrict__ Aout)
{
    extern __shared__ float sh[];
    float* Qs = sh;
    float* Ks = Qs + 64 * SSTR;
    float* Vs = Ks + 64 * SSTR;
    float* Ps = Vs + 64 * SSTR;

    int qb = blockIdx.x;
    int bh = blockIdx.y;
    int tid = threadIdx.x;
    int tc = tid & 15, tr = tid >> 4;
    int r0 = tr * 4;
    int c0 = tc * 4;

    const float* qbase = Q  + ((size_t)bh * TT + (size_t)qb * BQ) * HD;
    const float* kbase = Kp + (size_t)bh * TT * HD;
    const float* vbase = Vp + (size_t)bh * TT * HD;

    for (int idx = tid; idx < BQ * HD; idx += 256)
        Qs[(idx >> 6) * SSTR + (idx & 63)] = qbase[idx];

    float m_i[4], l_i[4], O[4][4];
    #pragma unroll
    for (int i = 0; i < 4; i++) {
        m_i[i] = -1e30f; l_i[i] = 0.f;
        #pragma unroll
        for (int d = 0; d < 4; d++) O[i][d] = 0.f;
    }

    int ntiles = qb + 1;
    for (int kt = 0; kt < ntiles; kt++) {
        __syncthreads();
        for (int idx = tid; idx < BQ * HD; idx += 256) {
            int rr = idx >> 6, cc = idx & 63;
            Ks[rr * SSTR + cc] = kbase[(size_t)kt * BQ * HD + idx];
            Vs[rr * SSTR + cc] = vbase[(size_t)kt * BQ * HD + idx];
        }
        __syncthreads();

        float s[4][4];
        #pragma unroll
        for (int i = 0; i < 4; i++)
            #pragma unroll
            for (int j = 0; j < 4; j++) s[i][j] = 0.f;

        #pragma unroll 8
        for (int k = 0; k < HD; k++) {
            float a[4], bbr[4];
            #pragma unroll
            for (int i = 0; i < 4; i++) a[i]   = Qs[(r0 + i) * SSTR + k];
            #pragma unroll
            for (int j = 0; j < 4; j++) bbr[j] = Ks[(c0 + j) * SSTR + k];
            #pragma unroll
            for (int i = 0; i < 4; i++)
                #pragma unroll
                for (int j = 0; j < 4; j++)
                    s[i][j] = fmaf(a[i], bbr[j], s[i][j]);
        }

        if (kt == qb) {
            #pragma unroll
            for (int i = 0; i < 4; i++)
                #pragma unroll
                for (int j = 0; j < 4; j++)
                    if (c0 + j > r0 + i) s[i][j] = -1e30f;
        }

        #pragma unroll
        for (int i = 0; i < 4; i++) {
            float mx = s[i][0];
            #pragma unroll
            for (int j = 1; j < 4; j++) mx = fmaxf(mx, s[i][j]);
            mx = fmaxf(mx, __shfl_xor_sync(0xffffffffu, mx, 1));
            mx = fmaxf(mx, __shfl_xor_sync(0xffffffffu, mx, 2));
            mx = fmaxf(mx, __shfl_xor_sync(0xffffffffu, mx, 4));
            mx = fmaxf(mx, __shfl_xor_sync(0xffffffffu, mx, 8));
            float m_new = fmaxf(m_i[i], mx);
            float sum = 0.f;
            #pragma unroll
            for (int j = 0; j < 4; j++) {
                s[i][j] = __expf(s[i][j] - m_new);
                sum += s[i][j];
            }
            sum += __shfl_xor_sync(0xffffffffu, sum, 1);
            sum += __shfl_xor_sync(0xffffffffu, sum, 2);
            sum += __shfl_xor_sync(0xffffffffu, sum, 4);
            sum += __shfl_xor_sync(0xffffffffu, sum, 8);
            float alpha = __expf(m_i[i] - m_new);
            l_i[i] = l_i[i] * alpha + sum;
            m_i[i] = m_new;
            #pragma unroll
            for (int d = 0; d < 4; d++) O[i][d] *= alpha;
            #pragma unroll
            for (int j = 0; j < 4; j++)
                Ps[(r0 + i) * SSTR + c0 + j] = s[i][j];
        }
        __syncthreads();

        #pragma unroll 8
        for (int j = 0; j < BQ; j++) {
            float p[4], v[4];
            #pragma unroll
            for (int i = 0; i < 4; i++) p[i] = Ps[(r0 + i) * SSTR + j];
            #pragma unroll
            for (int d = 0; d < 4; d++) v[d] = Vs[j * SSTR + c0 + d];
            #pragma unroll
            for (int i = 0; i < 4; i++)
                #pragma unroll
                for (int d = 0; d < 4; d++)
                    O[i][d] = fmaf(p[i], v[d], O[i][d]);
        }
    }

    int batch = bh >> 4, h = bh & 15;
    #pragma unroll
    for (int i = 0; i < 4; i++) {
        int t = qb * BQ + r0 + i;
        float inv = 1.0f / l_i[i];
        float4 o4 = make_float4(O[i][0] * inv, O[i][1] * inv, O[i][2] * inv, O[i][3] * inv);
        *(float4*)(Aout + ((size_t)batch * TT + t) * HH + h * HD + c0) = o4;
    }
}

// ---------------------------------------------------------------------------
// Launch
// ---------------------------------------------------------------------------
extern "C" void kernel_launch(void* const* d_in, const int* in_sizes, int n_in,
                              void* d_out, int out_size)
{
    const float* x       = (const float*)d_in[0];
    const float* w_attn  = (const float*)d_in[1];
    const float* b_attn  = (const float*)d_in[2];
    const float* w_aproj = (const float*)d_in[3];
    const float* b_aproj = (const float*)d_in[4];
    const float* ln1_w   = (const float*)d_in[5];
    const float* ln1_b   = (const float*)d_in[6];
    const float* ln2_w   = (const float*)d_in[7];
    const float* ln2_b   = (const float*)d_in[8];
    const float* w_fc    = (const float*)d_in[9];
    const float* b_fc    = (const float*)d_in[10];
    const float* w_mproj = (const float*)d_in[11];
    const float* b_mproj = (const float*)d_in[12];

    float* out_x = (float*)d_out;
    float* pk = out_x + (size_t)MM * HH;
    float* pv = pk + (size_t)MM * HH;

    float *xn, *q, *a, *x1, *h;
    cudaGetSymbolAddress((void**)&xn, g_xn);
    cudaGetSymbolAddress((void**)&q,  g_q);
    cudaGetSymbolAddress((void**)&a,  g_a);
    cudaGetSymbolAddress((void**)&x1, g_x1);
    cudaGetSymbolAddress((void**)&h,  g_h);

    groupnorm_kernel<<<BB * NGRP, 256>>>(x, ln1_w, ln1_b, xn);

    tgemm_kernel<0><<<dim3(3 * HH / GBN, MM / GBM), 256>>>(
        xn, w_attn, b_attn, nullptr, q, pk, pv, MM, 3 * HH, HH);

    size_t shmem = 4 * 64 * SSTR * sizeof(float);
    cudaFuncSetAttribute(flash_kernel, cudaFuncAttributeMaxDynamicSharedMemorySize, (int)shmem);
    flash_kernel<<<dim3(TT / BQ, BB * NH), 256, shmem>>>(q, pk, pv, a);

    tgemm_kernel<1><<<dim3(HH / GBN, MM / GBM), 256>>>(
        a, w_aproj, b_aproj, x, x1, nullptr, nullptr, MM, HH, HH);

    groupnorm_kernel<<<BB * NGRP, 256>>>(x1, ln2_w, ln2_b, xn);

    tgemm_kernel<2><<<dim3(4 * HH / GBN, MM / GBM), 256>>>(
        xn, w_fc, b_fc, nullptr, h, nullptr, nullptr, MM, 4 * HH, HH);

    tgemm_kernel<1><<<dim3(HH / GBN, MM / GBM), 256>>>(
        h, w_mproj, b_mproj, x1, out_x, nullptr, nullptr, MM, HH, 4 * HH);
}

// round 4
// speedup vs baseline: 2.1267x; 1.3205x over previous
#include <cuda_runtime.h>
#include <cuda_bf16.h>
#include <math.h>

// Problem constants
#define BB   2
#define TT   2048
#define HH   1024
#define NH   16
#define HD   64
#define MM   (BB*TT)        // 4096
#define NGRP 32
#define GSZ  (HH/NGRP)      // 32
#define GELEM (TT*GSZ)      // 65536

// Scratch (device globals; no allocation allowed)
__device__ float g_xn[MM*HH];
__device__ float g_q [MM*HH];
__device__ float g_a [MM*HH];
__device__ float g_x1[MM*HH];
__device__ float g_h [MM*4*HH];

// ---------------------------------------------------------------------------
// GroupNorm
// ---------------------------------------------------------------------------
__global__ void groupnorm_kernel(const float* __restrict__ x,
                                 const float* __restrict__ w,
                                 const float* __restrict__ b,
                                 float* __restrict__ y)
{
    int bg = blockIdx.x;
    int batch = bg >> 5;
    int g = bg & 31;
    const float* xp = x + (size_t)batch * TT * HH + g * GSZ;
    float* yp       = y + (size_t)batch * TT * HH + g * GSZ;

    float s = 0.f, ss = 0.f;
    for (int idx = threadIdx.x; idx < GELEM; idx += 256) {
        int t = idx >> 5, c = idx & 31;
        float v = xp[(size_t)t * HH + c];
        s += v; ss += v * v;
    }
    __shared__ float rs[256], rss[256];
    rs[threadIdx.x] = s; rss[threadIdx.x] = ss;
    __syncthreads();
    for (int o = 128; o > 0; o >>= 1) {
        if (threadIdx.x < o) {
            rs[threadIdx.x]  += rs[threadIdx.x + o];
            rss[threadIdx.x] += rss[threadIdx.x + o];
        }
        __syncthreads();
    }
    __shared__ float s_mean, s_rstd;
    if (threadIdx.x == 0) {
        float mean = rs[0] * (1.0f / GELEM);
        float var  = rss[0] * (1.0f / GELEM) - mean * mean;
        s_mean = mean;
        s_rstd = rsqrtf(var + 1e-5f);
    }
    __syncthreads();
    float mean = s_mean, rstd = s_rstd;
    for (int idx = threadIdx.x; idx < GELEM; idx += 256) {
        int t = idx >> 5, c = idx & 31;
        int ch = g * GSZ + c;
        float v = xp[(size_t)t * HH + c];
        yp[(size_t)t * HH + c] = (v - mean) * rstd * w[ch] + b[ch];
    }
}

// ---------------------------------------------------------------------------
// TF32 tensor-core GEMM, cp.async 2-stage pipeline.
// BM=BN=128, BK=32, 256 threads (8 warps), warp tile 64x32, m16n8k8.
// A stored [m][k] pad 36, B stored [k][n] pad 136 (both conflict-free frags).
// ---------------------------------------------------------------------------
#define GBM 128
#define GBN 128
#define GBK 32
#define APAD 36
#define BPAD 136
#define A_STG (GBM*APAD)          // 4608 floats
#define B_STG (GBK*BPAD)          // 4352 floats
#define STG   (A_STG + B_STG)     // 8960 floats = 35840 B per stage

__device__ __forceinline__ float gelu_f(float v) {
    const float c = 0.7978845608028654f;
    float u = c * (v + 0.044715f * v * v * v);
    return 0.5f * v * (1.0f + tanhf(u));
}

__device__ __forceinline__ unsigned f2tf(float x) {
    unsigned u;
    asm("cvt.rna.tf32.f32 %0, %1;" : "=r"(u) : "f"(x));
    return u;
}

__device__ __forceinline__ void mma_tf32(float* d, const unsigned* a, const unsigned* b) {
    asm volatile(
        "mma.sync.aligned.m16n8k8.row.col.f32.tf32.tf32.f32 "
        "{%0,%1,%2,%3}, {%4,%5,%6,%7}, {%8,%9}, {%0,%1,%2,%3};"
        : "+f"(d[0]), "+f"(d[1]), "+f"(d[2]), "+f"(d[3])
        : "r"(a[0]), "r"(a[1]), "r"(a[2]), "r"(a[3]),
          "r"(b[0]), "r"(b[1]));
}

__device__ __forceinline__ void cp16(float* dst, const float* src) {
    unsigned d = (unsigned)__cvta_generic_to_shared(dst);
    asm volatile("cp.async.cg.shared.global [%0], [%1], 16;" :: "r"(d), "l"(src));
}

template<int MODE>
__global__ void __launch_bounds__(256, 2)
tgemm_kernel(const float* __restrict__ A, const float* __restrict__ Bm,
             const float* __restrict__ bias, const float* __restrict__ res,
             float* __restrict__ C, float* __restrict__ C2, float* __restrict__ C3,
             int M, int N, int K)
{
    extern __shared__ float sh[];

    int tid  = threadIdx.x;
    int wid  = tid >> 5;
    int lane = tid & 31;
    int wm = wid >> 2;          // 0..1
    int wn = wid & 3;           // 0..3
    int lr = lane >> 2;         // 0..7
    int lc = lane & 3;          // 0..3

    int bm = blockIdx.y * GBM, bn = blockIdx.x * GBN;
    const float* Aptr = A + (size_t)bm * K;
    const float* Bptr = Bm + bn;

    float acc[4][4][4];
    #pragma unroll
    for (int i = 0; i < 4; i++)
        #pragma unroll
        for (int j = 0; j < 4; j++)
            #pragma unroll
            for (int e = 0; e < 4; e++) acc[i][j][e] = 0.f;

    // load-index precompute
    int a_row = tid >> 3, a_off = (tid & 7) * 4;     // + r*32 rows per pass
    int b_row = tid >> 6, b_col = (tid & 63) * 2;    // unused mapping variant
    // B: 1024 chunks of 4 floats: chunk c -> row c>>5, col (c&31)*4
    int ntiles = K / GBK;

    // prologue: load tile 0 into stage 0
    {
        int k0 = 0;
        float* sA = sh;
        float* sB = sh + A_STG;
        #pragma unroll
        for (int r = 0; r < 4; r++) {
            int row = a_row + r * 32;
            cp16(&sA[row * APAD + a_off], Aptr + (size_t)row * K + k0 + a_off);
        }
        #pragma unroll
        for (int r = 0; r < 4; r++) {
            int c = tid + r * 256;
            int row = c >> 5, col = (c & 31) * 4;
            cp16(&sB[row * BPAD + col], Bptr + (size_t)(k0 + row) * N + col);
        }
        asm volatile("cp.async.commit_group;");
    }

    for (int it = 0; it < ntiles; it++) {
        asm volatile("cp.async.wait_group 0;");
        __syncthreads();

        // issue next tile into the other stage (overlaps with MMAs below)
        if (it + 1 < ntiles) {
            int k0 = (it + 1) * GBK;
            float* sA = sh + ((it + 1) & 1) * STG;
            float* sB = sA + A_STG;
            #pragma unroll
            for (int r = 0; r < 4; r++) {
                int row = a_row + r * 32;
                cp16(&sA[row * APAD + a_off], Aptr + (size_t)row * K + k0 + a_off);
            }
            #pragma unroll
            for (int r = 0; r < 4; r++) {
                int c = tid + r * 256;
                int row = c >> 5, col = (c & 31) * 4;
                cp16(&sB[row * BPAD + col], Bptr + (size_t)(k0 + row) * N + col);
            }
        }
        asm volatile("cp.async.commit_group;");

        // compute current stage
        const float* As = sh + (it & 1) * STG;
        const float* Bs = As + A_STG;

        #pragma unroll
        for (int kk = 0; kk < GBK / 8; kk++) {
            int kb = kk * 8;
            unsigned af[4][4], bf[4][2];
            #pragma unroll
            for (int i = 0; i < 4; i++) {
                int m0 = wm * 64 + i * 16 + lr;
                af[i][0] = f2tf(As[(size_t)m0 * APAD + kb + lc]);
                af[i][1] = f2tf(As[(size_t)(m0 + 8) * APAD + kb + lc]);
                af[i][2] = f2tf(As[(size_t)m0 * APAD + kb + lc + 4]);
                af[i][3] = f2tf(As[(size_t)(m0 + 8) * APAD + kb + lc + 4]);
            }
            #pragma unroll
            for (int j = 0; j < 4; j++) {
                int n0 = wn * 32 + j * 8 + lr;
                bf[j][0] = f2tf(Bs[(size_t)(kb + lc) * BPAD + n0]);
                bf[j][1] = f2tf(Bs[(size_t)(kb + lc + 4) * BPAD + n0]);
            }
            #pragma unroll
            for (int i = 0; i < 4; i++)
                #pragma unroll
                for (int j = 0; j < 4; j++)
                    mma_tf32(acc[i][j], af[i], bf[j]);
        }
        __syncthreads();
    }

    // Epilogue. c0:(r,c) c1:(r,c+1) c2:(r+8,c) c3:(r+8,c+1)
    #pragma unroll
    for (int i = 0; i < 4; i++) {
        int rbase = bm + wm * 64 + i * 16 + lr;
        #pragma unroll
        for (int j = 0; j < 4; j++) {
            int cbase = bn + wn * 32 + j * 8 + 2 * lc;
            #pragma unroll
            for (int e = 0; e < 4; e++) {
                int m = rbase + (e >> 1) * 8;
                int n = cbase + (e & 1);
                float val = acc[i][j][e] + bias[n];
                if (MODE == 0) {
                    int bidx = m >> 11, t = m & 2047;
                    int part = n >> 10;
                    int nn = n & 1023;
                    int h = nn >> 6, d = nn & 63;
                    size_t idx = ((((size_t)bidx * NH + h) * TT) + t) * HD + d;
                    if (part == 0)      C [idx] = val;
                    else if (part == 1) C2[idx] = val;
                    else                C3[idx] = val;
                } else if (MODE == 1) {
                    size_t idx = (size_t)m * N + n;
                    C[idx] = val + res[idx];
                } else {
                    C[(size_t)m * N + n] = gelu_f(val);
                }
            }
        }
    }
}

// ---------------------------------------------------------------------------
// Flash attention (fp32, no scale, causal). Unchanged.
// ---------------------------------------------------------------------------
#define BQ 64
#define SSTR 65

__global__ void __launch_bounds__(256, 3)
flash_kernel(const float* __restrict__ Q, const float* __restrict__ Kp,
             const float* __restrict__ Vp, float* __restrict__ Aout)
{
    extern __shared__ float sh[];
    float* Qs = sh;
    float* Ks = Qs + 64 * SSTR;
    float* Vs = Ks + 64 * SSTR;
    float* Ps = Vs + 64 * SSTR;

    int qb = blockIdx.x;
    int bh = blockIdx.y;
    int tid = threadIdx.x;
    int tc = tid & 15, tr = tid >> 4;
    int r0 = tr * 4;
    int c0 = tc * 4;

    const float* qbase = Q  + ((size_t)bh * TT + (size_t)qb * BQ) * HD;
    const float* kbase = Kp + (size_t)bh * TT * HD;
    const float* vbase = Vp + (size_t)bh * TT * HD;

    for (int idx = tid; idx < BQ * HD; idx += 256)
        Qs[(idx >> 6) * SSTR + (idx & 63)] = qbase[idx];

    float m_i[4], l_i[4], O[4][4];
    #pragma unroll
    for (int i = 0; i < 4; i++) {
        m_i[i] = -1e30f; l_i[i] = 0.f;
        #pragma unroll
        for (int d = 0; d < 4; d++) O[i][d] = 0.f;
    }

    int ntiles = qb + 1;
    for (int kt = 0; kt < ntiles; kt++) {
        __syncthreads();
        for (int idx = tid; idx < BQ * HD; idx += 256) {
            int rr = idx >> 6, cc = idx & 63;
            Ks[rr * SSTR + cc] = kbase[(size_t)kt * BQ * HD + idx];
            Vs[rr * SSTR + cc] = vbase[(size_t)kt * BQ * HD + idx];
        }
        __syncthreads();

        float s[4][4];
        #pragma unroll
        for (int i = 0; i < 4; i++)
            #pragma unroll
            for (int j = 0; j < 4; j++) s[i][j] = 0.f;

        #pragma unroll 8
        for (int k = 0; k < HD; k++) {
            float a[4], bbr[4];
            #pragma unroll
            for (int i = 0; i < 4; i++) a[i]   = Qs[(r0 + i) * SSTR + k];
            #pragma unroll
            for (int j = 0; j < 4; j++) bbr[j] = Ks[(c0 + j) * SSTR + k];
            #pragma unroll
            for (int i = 0; i < 4; i++)
                #pragma unroll
                for (int j = 0; j < 4; j++)
                    s[i][j] = fmaf(a[i], bbr[j], s[i][j]);
        }

        if (kt == qb) {
            #pragma unroll
            for (int i = 0; i < 4; i++)
                #pragma unroll
                for (int j = 0; j < 4; j++)
                    if (c0 + j > r0 + i) s[i][j] = -1e30f;
        }

        #pragma unroll
        for (int i = 0; i < 4; i++) {
            float mx = s[i][0];
            #pragma unroll
            for (int j = 1; j < 4; j++) mx = fmaxf(mx, s[i][j]);
            mx = fmaxf(mx, __shfl_xor_sync(0xffffffffu, mx, 1));
            mx = fmaxf(mx, __shfl_xor_sync(0xffffffffu, mx, 2));
            mx = fmaxf(mx, __shfl_xor_sync(0xffffffffu, mx, 4));
            mx = fmaxf(mx, __shfl_xor_sync(0xffffffffu, mx, 8));
            float m_new = fmaxf(m_i[i], mx);
            float sum = 0.f;
            #pragma unroll
            for (int j = 0; j < 4; j++) {
                s[i][j] = __expf(s[i][j] - m_new);
                sum += s[i][j];
            }
            sum += __shfl_xor_sync(0xffffffffu, sum, 1);
            sum += __shfl_xor_sync(0xffffffffu, sum, 2);
            sum += __shfl_xor_sync(0xffffffffu, sum, 4);
            sum += __shfl_xor_sync(0xffffffffu, sum, 8);
            float alpha = __expf(m_i[i] - m_new);
            l_i[i] = l_i[i] * alpha + sum;
            m_i[i] = m_new;
            #pragma unroll
            for (int d = 0; d < 4; d++) O[i][d] *= alpha;
            #pragma unroll
            for (int j = 0; j < 4; j++)
                Ps[(r0 + i) * SSTR + c0 + j] = s[i][j];
        }
        __syncthreads();

        #pragma unroll 8
        for (int j = 0; j < BQ; j++) {
            float p[4], v[4];
            #pragma unroll
            for (int i = 0; i < 4; i++) p[i] = Ps[(r0 + i) * SSTR + j];
            #pragma unroll
            for (int d = 0; d < 4; d++) v[d] = Vs[j * SSTR + c0 + d];
            #pragma unroll
            for (int i = 0; i < 4; i++)
                #pragma unroll
                for (int d = 0; d < 4; d++)
                    O[i][d] = fmaf(p[i], v[d], O[i][d]);
        }
    }

    int batch = bh >> 4, h = bh & 15;
    #pragma unroll
    for (int i = 0; i < 4; i++) {
        int t = qb * BQ + r0 + i;
        float inv = 1.0f / l_i[i];
        float4 o4 = make_float4(O[i][0] * inv, O[i][1] * inv, O[i][2] * inv, O[i][3] * inv);
        *(float4*)(Aout + ((size_t)batch * TT + t) * HH + h * HD + c0) = o4;
    }
}

// ---------------------------------------------------------------------------
// Launch
// ---------------------------------------------------------------------------
extern "C" void kernel_launch(void* const* d_in, const int* in_sizes, int n_in,
                              void* d_out, int out_size)
{
    const float* x       = (const float*)d_in[0];
    const float* w_attn  = (const float*)d_in[1];
    const float* b_attn  = (const float*)d_in[2];
    const float* w_aproj = (const float*)d_in[3];
    const float* b_aproj = (const float*)d_in[4];
    const float* ln1_w   = (const float*)d_in[5];
    const float* ln1_b   = (const float*)d_in[6];
    const float* ln2_w   = (const float*)d_in[7];
    const float* ln2_b   = (const float*)d_in[8];
    const float* w_fc    = (const float*)d_in[9];
    const float* b_fc    = (const float*)d_in[10];
    const float* w_mproj = (const float*)d_in[11];
    const float* b_mproj = (const float*)d_in[12];

    float* out_x = (float*)d_out;
    float* pk = out_x + (size_t)MM * HH;
    float* pv = pk + (size_t)MM * HH;

    float *xn, *q, *a, *x1, *h;
    cudaGetSymbolAddress((void**)&xn, g_xn);
    cudaGetSymbolAddress((void**)&q,  g_q);
    cudaGetSymbolAddress((void**)&a,  g_a);
    cudaGetSymbolAddress((void**)&x1, g_x1);
    cudaGetSymbolAddress((void**)&h,  g_h);

    size_t gsmem = 2 * STG * sizeof(float);   // 71680 B
    cudaFuncSetAttribute(tgemm_kernel<0>, cudaFuncAttributeMaxDynamicSharedMemorySize, (int)gsmem);
    cudaFuncSetAttribute(tgemm_kernel<1>, cudaFuncAttributeMaxDynamicSharedMemorySize, (int)gsmem);
    cudaFuncSetAttribute(tgemm_kernel<2>, cudaFuncAttributeMaxDynamicSharedMemorySize, (int)gsmem);

    groupnorm_kernel<<<BB * NGRP, 256>>>(x, ln1_w, ln1_b, xn);

    tgemm_kernel<0><<<dim3(3 * HH / GBN, MM / GBM), 256, gsmem>>>(
        xn, w_attn, b_attn, nullptr, q, pk, pv, MM, 3 * HH, HH);

    size_t shmem = 4 * 64 * SSTR * sizeof(float);
    cudaFuncSetAttribute(flash_kernel, cudaFuncAttributeMaxDynamicSharedMemorySize, (int)shmem);
    flash_kernel<<<dim3(TT / BQ, BB * NH), 256, shmem>>>(q, pk, pv, a);

    tgemm_kernel<1><<<dim3(HH / GBN, MM / GBM), 256, gsmem>>>(
        a, w_aproj, b_aproj, x, x1, nullptr, nullptr, MM, HH, HH);

    groupnorm_kernel<<<BB * NGRP, 256>>>(x1, ln2_w, ln2_b, xn);

    tgemm_kernel<2><<<dim3(4 * HH / GBN, MM / GBM), 256, gsmem>>>(
        xn, w_fc, b_fc, nullptr, h, nullptr, nullptr, MM, 4 * HH, HH);

    tgemm_kernel<1><<<dim3(HH / GBN, MM / GBM), 256, gsmem>>>(
        h, w_mproj, b_mproj, x1, out_x, nullptr, nullptr, MM, HH, 4 * HH);
}

// round 5
// speedup vs baseline: 3.3432x; 1.5721x over previous
#include <cuda_runtime.h>
#include <cuda_bf16.h>
#include <math.h>

// Problem constants
#define BB   2
#define TT   2048
#define HH   1024
#define NH   16
#define HD   64
#define MM   (BB*TT)        // 4096
#define NGRP 32
#define GSZ  (HH/NGRP)      // 32
#define GELEM (TT*GSZ)      // 65536

// Scratch (device globals; no allocation allowed)
__device__ float g_xn[MM*HH];
__device__ float g_q [MM*HH];        // q, tf32-rounded, [b,h,t,d]
__device__ float g_kr[MM*HH];        // k, tf32-rounded, [b,h,t,d]
__device__ float g_vt[MM*HH];        // v^T, tf32-rounded, [b,h,d,t]
__device__ float g_a [MM*HH];
__device__ float g_x1[MM*HH];
__device__ float g_h [MM*4*HH];
__device__ float g_wattn [HH*3*HH];  // tf32-rounded weights
__device__ float g_waproj[HH*HH];
__device__ float g_wfc   [HH*4*HH];
__device__ float g_wmproj[4*HH*HH];

__device__ __forceinline__ unsigned f2tf(float x) {
    unsigned u;
    asm("cvt.rna.tf32.f32 %0, %1;" : "=r"(u) : "f"(x));
    return u;
}
__device__ __forceinline__ float f2tff(float x) { return __uint_as_float(f2tf(x)); }

// ---------------------------------------------------------------------------
// Round weights to tf32 once per launch
// ---------------------------------------------------------------------------
__global__ void round_tf32_kernel(const float* __restrict__ in,
                                  float* __restrict__ out, int n4)
{
    int i = blockIdx.x * blockDim.x + threadIdx.x;
    int stride = gridDim.x * blockDim.x;
    for (; i < n4; i += stride) {
        float4 v = ((const float4*)in)[i];
        v.x = f2tff(v.x); v.y = f2tff(v.y); v.z = f2tff(v.z); v.w = f2tff(v.w);
        ((float4*)out)[i] = v;
    }
}

// ---------------------------------------------------------------------------
// GroupNorm (output tf32-rounded: it only feeds GEMM A operands)
// ---------------------------------------------------------------------------
__global__ void groupnorm_kernel(const float* __restrict__ x,
                                 const float* __restrict__ w,
                                 const float* __restrict__ b,
                                 float* __restrict__ y)
{
    int bg = blockIdx.x;
    int batch = bg >> 5;
    int g = bg & 31;
    const float* xp = x + (size_t)batch * TT * HH + g * GSZ;
    float* yp       = y + (size_t)batch * TT * HH + g * GSZ;

    float s = 0.f, ss = 0.f;
    for (int idx = threadIdx.x; idx < GELEM; idx += 256) {
        int t = idx >> 5, c = idx & 31;
        float v = xp[(size_t)t * HH + c];
        s += v; ss += v * v;
    }
    __shared__ float rs[256], rss[256];
    rs[threadIdx.x] = s; rss[threadIdx.x] = ss;
    __syncthreads();
    for (int o = 128; o > 0; o >>= 1) {
        if (threadIdx.x < o) {
            rs[threadIdx.x]  += rs[threadIdx.x + o];
            rss[threadIdx.x] += rss[threadIdx.x + o];
        }
        __syncthreads();
    }
    __shared__ float s_mean, s_rstd;
    if (threadIdx.x == 0) {
        float mean = rs[0] * (1.0f / GELEM);
        float var  = rss[0] * (1.0f / GELEM) - mean * mean;
        s_mean = mean;
        s_rstd = rsqrtf(var + 1e-5f);
    }
    __syncthreads();
    float mean = s_mean, rstd = s_rstd;
    for (int idx = threadIdx.x; idx < GELEM; idx += 256) {
        int t = idx >> 5, c = idx & 31;
        int ch = g * GSZ + c;
        float v = xp[(size_t)t * HH + c];
        yp[(size_t)t * HH + c] = f2tff((v - mean) * rstd * w[ch] + b[ch]);
    }
}

// ---------------------------------------------------------------------------
// TF32 tensor-core GEMM, cp.async 2-stage pipeline; operands pre-rounded.
// ---------------------------------------------------------------------------
#define GBM 128
#define GBN 128
#define GBK 32
#define APAD 36
#define BPAD 136
#define A_STG (GBM*APAD)
#define B_STG (GBK*BPAD)
#define STG   (A_STG + B_STG)

__device__ __forceinline__ float gelu_f(float v) {
    const float c = 0.7978845608028654f;
    float u = c * (v + 0.044715f * v * v * v);
    return 0.5f * v * (1.0f + tanhf(u));
}

__device__ __forceinline__ void mma_tf32(float* d, const unsigned* a, const unsigned* b) {
    asm volatile(
        "mma.sync.aligned.m16n8k8.row.col.f32.tf32.tf32.f32 "
        "{%0,%1,%2,%3}, {%4,%5,%6,%7}, {%8,%9}, {%0,%1,%2,%3};"
        : "+f"(d[0]), "+f"(d[1]), "+f"(d[2]), "+f"(d[3])
        : "r"(a[0]), "r"(a[1]), "r"(a[2]), "r"(a[3]),
          "r"(b[0]), "r"(b[1]));
}

__device__ __forceinline__ void cp16(float* dst, const float* src) {
    unsigned d = (unsigned)__cvta_generic_to_shared(dst);
    asm volatile("cp.async.cg.shared.global [%0], [%1], 16;" :: "r"(d), "l"(src));
}

template<int MODE>
__global__ void __launch_bounds__(256, 2)
tgemm_kernel(const float* __restrict__ A, const float* __restrict__ Bm,
             const float* __restrict__ bias, const float* __restrict__ res,
             float* __restrict__ C, float* __restrict__ C2, float* __restrict__ C3,
             float* __restrict__ KR, float* __restrict__ VT,
             int M, int N, int K)
{
    extern __shared__ float sh[];

    int tid  = threadIdx.x;
    int wid  = tid >> 5;
    int lane = tid & 31;
    int wm = wid >> 2;
    int wn = wid & 3;
    int lr = lane >> 2;
    int lc = lane & 3;

    int bm = blockIdx.y * GBM, bn = blockIdx.x * GBN;
    const float* Aptr = A + (size_t)bm * K;
    const float* Bptr = Bm + bn;

    float acc[4][4][4];
    #pragma unroll
    for (int i = 0; i < 4; i++)
        #pragma unroll
        for (int j = 0; j < 4; j++)
            #pragma unroll
            for (int e = 0; e < 4; e++) acc[i][j][e] = 0.f;

    int a_row = tid >> 3, a_off = (tid & 7) * 4;
    int ntiles = K / GBK;

    {
        float* sA = sh;
        float* sB = sh + A_STG;
        #pragma unroll
        for (int r = 0; r < 4; r++) {
            int row = a_row + r * 32;
            cp16(&sA[row * APAD + a_off], Aptr + (size_t)row * K + a_off);
        }
        #pragma unroll
        for (int r = 0; r < 4; r++) {
            int c = tid + r * 256;
            int row = c >> 5, col = (c & 31) * 4;
            cp16(&sB[row * BPAD + col], Bptr + (size_t)row * N + col);
        }
        asm volatile("cp.async.commit_group;");
    }

    for (int it = 0; it < ntiles; it++) {
        asm volatile("cp.async.wait_group 0;");
        __syncthreads();

        if (it + 1 < ntiles) {
            int k0 = (it + 1) * GBK;
            float* sA = sh + ((it + 1) & 1) * STG;
            float* sB = sA + A_STG;
            #pragma unroll
            for (int r = 0; r < 4; r++) {
                int row = a_row + r * 32;
                cp16(&sA[row * APAD + a_off], Aptr + (size_t)row * K + k0 + a_off);
            }
            #pragma unroll
            for (int r = 0; r < 4; r++) {
                int c = tid + r * 256;
                int row = c >> 5, col = (c & 31) * 4;
                cp16(&sB[row * BPAD + col], Bptr + (size_t)(k0 + row) * N + col);
            }
        }
        asm volatile("cp.async.commit_group;");

        const float* As = sh + (it & 1) * STG;
        const float* Bs = As + A_STG;

        #pragma unroll
        for (int kk = 0; kk < GBK / 8; kk++) {
            int kb = kk * 8;
            unsigned af[4][4], bf[4][2];
            #pragma unroll
            for (int i = 0; i < 4; i++) {
                int m0 = wm * 64 + i * 16 + lr;
                af[i][0] = __float_as_uint(As[(size_t)m0 * APAD + kb + lc]);
                af[i][1] = __float_as_uint(As[(size_t)(m0 + 8) * APAD + kb + lc]);
                af[i][2] = __float_as_uint(As[(size_t)m0 * APAD + kb + lc + 4]);
                af[i][3] = __float_as_uint(As[(size_t)(m0 + 8) * APAD + kb + lc + 4]);
            }
            #pragma unroll
            for (int j = 0; j < 4; j++) {
                int n0 = wn * 32 + j * 8 + lr;
                bf[j][0] = __float_as_uint(Bs[(size_t)(kb + lc) * BPAD + n0]);
                bf[j][1] = __float_as_uint(Bs[(size_t)(kb + lc + 4) * BPAD + n0]);
            }
            #pragma unroll
            for (int i = 0; i < 4; i++)
                #pragma unroll
                for (int j = 0; j < 4; j++)
                    mma_tf32(acc[i][j], af[i], bf[j]);
        }
        __syncthreads();
    }

    #pragma unroll
    for (int i = 0; i < 4; i++) {
        int rbase = bm + wm * 64 + i * 16 + lr;
        #pragma unroll
        for (int j = 0; j < 4; j++) {
            int cbase = bn + wn * 32 + j * 8 + 2 * lc;
            #pragma unroll
            for (int e = 0; e < 4; e++) {
                int m = rbase + (e >> 1) * 8;
                int n = cbase + (e & 1);
                float val = acc[i][j][e] + bias[n];
                if (MODE == 0) {
                    int bidx = m >> 11, t = m & 2047;
                    int part = n >> 10;
                    int nn = n & 1023;
                    int h = nn >> 6, d = nn & 63;
                    size_t idx = ((((size_t)bidx * NH + h) * TT) + t) * HD + d;
                    if (part == 0) {
                        C[idx] = f2tff(val);              // q: rounded, scratch only
                    } else if (part == 1) {
                        C2[idx] = val;                    // present k: exact
                        KR[idx] = f2tff(val);             // rounded copy for flash
                    } else {
                        C3[idx] = val;                    // present v: exact
                        size_t vt = (((size_t)bidx * NH + h) * HD + d) * TT + t;
                        VT[vt] = f2tff(val);              // rounded transposed copy
                    }
                } else if (MODE == 1) {
                    size_t idx = (size_t)m * N + n;
                    C[idx] = val + res[idx];
                } else {
                    C[(size_t)m * N + n] = f2tff(gelu_f(val));
                }
            }
        }
    }
}

// ---------------------------------------------------------------------------
// Flash attention, tf32 tensor cores. 64x64 tiles, hd=64.
// 4 warps, each owns a 16-row strip. grid (32 qtiles, 32 bh), 128 threads.
// ---------------------------------------------------------------------------
#define FP 68    // smem row pad (stride 68: frag banks = 4*lr+lc, conflict-free)

__global__ void __launch_bounds__(128, 3)
flash_kernel(const float* __restrict__ Q, const float* __restrict__ Kr,
             const float* __restrict__ Vt, float* __restrict__ Aout)
{
    extern __shared__ float sh[];
    float* Ks = sh;               // [64][68]  K rows [j][d]
    float* Vs = Ks + 64 * FP;     // [64][68]  V^T rows [d][j]
    float* Ps = Vs + 64 * FP;     // [64][68]  P rows [r][j]

    int qb = blockIdx.x;
    int bh = blockIdx.y;
    int tid = threadIdx.x;
    int w   = tid >> 5;           // warp 0..3 -> rows w*16..w*16+15
    int lane = tid & 31;
    int lr = lane >> 2;           // 0..7
    int lc = lane & 3;            // 0..3

    const float* qbase  = Q  + ((size_t)bh * TT + (size_t)qb * 64 + w * 16) * HD;
    const float* kbase  = Kr + (size_t)bh * TT * HD;
    const float* vtbase = Vt + (size_t)bh * HD * TT;

    // Q fragments (pre-rounded): qf[kb] covers cols kb*8 + {lc, lc+4}
    unsigned qf[8][4];
    #pragma unroll
    for (int kb = 0; kb < 8; kb++) {
        qf[kb][0] = __float_as_uint(qbase[(size_t)lr * HD + kb * 8 + lc]);
        qf[kb][1] = __float_as_uint(qbase[(size_t)(lr + 8) * HD + kb * 8 + lc]);
        qf[kb][2] = __float_as_uint(qbase[(size_t)lr * HD + kb * 8 + lc + 4]);
        qf[kb][3] = __float_as_uint(qbase[(size_t)(lr + 8) * HD + kb * 8 + lc + 4]);
    }

    float oacc[8][4];
    #pragma unroll
    for (int nb = 0; nb < 8; nb++)
        #pragma unroll
        for (int e = 0; e < 4; e++) oacc[nb][e] = 0.f;
    float m0 = -1e30f, m1 = -1e30f, l0 = 0.f, l1 = 0.f;

    for (int kt = 0; kt <= qb; kt++) {
        __syncthreads();   // previous iteration done with Ks/Vs
        // fill K tile and V^T tile via cp.async (data pre-rounded)
        #pragma unroll
        for (int i = 0; i < 8; i++) {
            int c = tid + i * 128;          // 0..1023 chunks of 4 floats
            int rw = c >> 4, c4 = (c & 15) * 4;
            cp16(&Ks[rw * FP + c4], kbase + ((size_t)kt * 64 + rw) * HD + c4);
            cp16(&Vs[rw * FP + c4], vtbase + (size_t)rw * TT + kt * 64 + c4);
        }
        asm volatile("cp.async.commit_group;");
        asm volatile("cp.async.wait_group 0;");
        __syncthreads();

        // S = Q @ K^T  (8 n-blocks of 8 cols)
        float sacc[8][4];
        #pragma unroll
        for (int nb = 0; nb < 8; nb++)
            #pragma unroll
            for (int e = 0; e < 4; e++) sacc[nb][e] = 0.f;

        #pragma unroll
        for (int kb = 0; kb < 8; kb++) {
            unsigned bf[8][2];
            #pragma unroll
            for (int nb = 0; nb < 8; nb++) {
                bf[nb][0] = __float_as_uint(Ks[(nb * 8 + lr) * FP + kb * 8 + lc]);
                bf[nb][1] = __float_as_uint(Ks[(nb * 8 + lr) * FP + kb * 8 + lc + 4]);
            }
            #pragma unroll
            for (int nb = 0; nb < 8; nb++)
                mma_tf32(sacc[nb], qf[kb], bf[nb]);
        }

        // causal mask on diagonal tile
        if (kt == qb) {
            int r0 = w * 16 + lr, r1 = r0 + 8;
            #pragma unroll
            for (int nb = 0; nb < 8; nb++) {
                int c0 = nb * 8 + 2 * lc, c1 = c0 + 1;
                if (c0 > r0) sacc[nb][0] = -1e30f;
                if (c1 > r0) sacc[nb][1] = -1e30f;
                if (c0 > r1) sacc[nb][2] = -1e30f;
                if (c1 > r1) sacc[nb][3] = -1e30f;
            }
        }

        // online softmax (rows lr and lr+8 of this warp's strip)
        float mx0 = -1e30f, mx1 = -1e30f;
        #pragma unroll
        for (int nb = 0; nb < 8; nb++) {
            mx0 = fmaxf(mx0, fmaxf(sacc[nb][0], sacc[nb][1]));
            mx1 = fmaxf(mx1, fmaxf(sacc[nb][2], sacc[nb][3]));
        }
        mx0 = fmaxf(mx0, __shfl_xor_sync(0xffffffffu, mx0, 1));
        mx0 = fmaxf(mx0, __shfl_xor_sync(0xffffffffu, mx0, 2));
        mx1 = fmaxf(mx1, __shfl_xor_sync(0xffffffffu, mx1, 1));
        mx1 = fmaxf(mx1, __shfl_xor_sync(0xffffffffu, mx1, 2));

        float mn0 = fmaxf(m0, mx0), mn1 = fmaxf(m1, mx1);
        float al0 = __expf(m0 - mn0), al1 = __expf(m1 - mn1);
        float sum0 = 0.f, sum1 = 0.f;
        #pragma unroll
        for (int nb = 0; nb < 8; nb++) {
            float p0 = __expf(sacc[nb][0] - mn0);
            float p1 = __expf(sacc[nb][1] - mn0);
            float p2 = __expf(sacc[nb][2] - mn1);
            float p3 = __expf(sacc[nb][3] - mn1);
            sum0 += p0 + p1; sum1 += p2 + p3;
            float2 v0 = make_float2(__uint_as_float(f2tf(p0)), __uint_as_float(f2tf(p1)));
            float2 v1 = make_float2(__uint_as_float(f2tf(p2)), __uint_as_float(f2tf(p3)));
            *(float2*)&Ps[(w * 16 + lr) * FP + nb * 8 + 2 * lc] = v0;
            *(float2*)&Ps[(w * 16 + lr + 8) * FP + nb * 8 + 2 * lc] = v1;
        }
        sum0 += __shfl_xor_sync(0xffffffffu, sum0, 1);
        sum0 += __shfl_xor_sync(0xffffffffu, sum0, 2);
        sum1 += __shfl_xor_sync(0xffffffffu, sum1, 1);
        sum1 += __shfl_xor_sync(0xffffffffu, sum1, 2);
        l0 = l0 * al0 + sum0; l1 = l1 * al1 + sum1;
        m0 = mn0; m1 = mn1;
        #pragma unroll
        for (int nb = 0; nb < 8; nb++) {
            oacc[nb][0] *= al0; oacc[nb][1] *= al0;
            oacc[nb][2] *= al1; oacc[nb][3] *= al1;
        }

        // O += P @ V   (A = P from smem, B = V^T rows)
        #pragma unroll
        for (int kb = 0; kb < 8; kb++) {
            unsigned af[4];
            af[0] = __float_as_uint(Ps[(w * 16 + lr) * FP + kb * 8 + lc]);
            af[1] = __float_as_uint(Ps[(w * 16 + lr + 8) * FP + kb * 8 + lc]);
            af[2] = __float_as_uint(Ps[(w * 16 + lr) * FP + kb * 8 + lc + 4]);
            af[3] = __float_as_uint(Ps[(w * 16 + lr + 8) * FP + kb * 8 + lc + 4]);
            #pragma unroll
            for (int nb = 0; nb < 8; nb++) {
                unsigned bf[2];
                bf[0] = __float_as_uint(Vs[(nb * 8 + lr) * FP + kb * 8 + lc]);
                bf[1] = __float_as_uint(Vs[(nb * 8 + lr) * FP + kb * 8 + lc + 4]);
                mma_tf32(oacc[nb], af, bf);
            }
        }
    }

    // write out (rounded: a only feeds aproj GEMM)
    int batch = bh >> 4, h = bh & 15;
    float inv0 = 1.0f / l0, inv1 = 1.0f / l1;
    int t0 = qb * 64 + w * 16 + lr;
    #pragma unroll
    for (int nb = 0; nb < 8; nb++) {
        int d0 = h * HD + nb * 8 + 2 * lc;
        float2 o0 = make_float2(f2tff(oacc[nb][0] * inv0), f2tff(oacc[nb][1] * inv0));
        float2 o1 = make_float2(f2tff(oacc[nb][2] * inv1), f2tff(oacc[nb][3] * inv1));
        *(float2*)(Aout + ((size_t)batch * TT + t0) * HH + d0) = o0;
        *(float2*)(Aout + ((size_t)batch * TT + t0 + 8) * HH + d0) = o1;
    }
}

// ---------------------------------------------------------------------------
// Launch
// ---------------------------------------------------------------------------
extern "C" void kernel_launch(void* const* d_in, const int* in_sizes, int n_in,
                              void* d_out, int out_size)
{
    const float* x       = (const float*)d_in[0];
    const float* w_attn  = (const float*)d_in[1];
    const float* b_attn  = (const float*)d_in[2];
    const float* w_aproj = (const float*)d_in[3];
    const float* b_aproj = (const float*)d_in[4];
    const float* ln1_w   = (const float*)d_in[5];
    const float* ln1_b   = (const float*)d_in[6];
    const float* ln2_w   = (const float*)d_in[7];
    const float* ln2_b   = (const float*)d_in[8];
    const float* w_fc    = (const float*)d_in[9];
    const float* b_fc    = (const float*)d_in[10];
    const float* w_mproj = (const float*)d_in[11];
    const float* b_mproj = (const float*)d_in[12];

    float* out_x = (float*)d_out;
    float* pk = out_x + (size_t)MM * HH;
    float* pv = pk + (size_t)MM * HH;

    float *xn, *q, *kr, *vt, *a, *x1, *h;
    float *wattn, *waproj, *wfc, *wmproj;
    cudaGetSymbolAddress((void**)&xn, g_xn);
    cudaGetSymbolAddress((void**)&q,  g_q);
    cudaGetSymbolAddress((void**)&kr, g_kr);
    cudaGetSymbolAddress((void**)&vt, g_vt);
    cudaGetSymbolAddress((void**)&a,  g_a);
    cudaGetSymbolAddress((void**)&x1, g_x1);
    cudaGetSymbolAddress((void**)&h,  g_h);
    cudaGetSymbolAddress((void**)&wattn,  g_wattn);
    cudaGetSymbolAddress((void**)&waproj, g_waproj);
    cudaGetSymbolAddress((void**)&wfc,    g_wfc);
    cudaGetSymbolAddress((void**)&wmproj, g_wmproj);

    size_t gsmem = 2 * STG * sizeof(float);
    cudaFuncSetAttribute(tgemm_kernel<0>, cudaFuncAttributeMaxDynamicSharedMemorySize, (int)gsmem);
    cudaFuncSetAttribute(tgemm_kernel<1>, cudaFuncAttributeMaxDynamicSharedMemorySize, (int)gsmem);
    cudaFuncSetAttribute(tgemm_kernel<2>, cudaFuncAttributeMaxDynamicSharedMemorySize, (int)gsmem);
    size_t fsmem = 3 * 64 * FP * sizeof(float);
    cudaFuncSetAttribute(flash_kernel, cudaFuncAttributeMaxDynamicSharedMemorySize, (int)fsmem);

    // round weights to tf32 (once per launch; graph-capturable)
    round_tf32_kernel<<<512, 256>>>(w_attn,  wattn,  HH * 3 * HH / 4);
    round_tf32_kernel<<<512, 256>>>(w_aproj, waproj, HH * HH / 4);
    round_tf32_kernel<<<512, 256>>>(w_fc,    wfc,    HH * 4 * HH / 4);
    round_tf32_kernel<<<512, 256>>>(w_mproj, wmproj, 4 * HH * HH / 4);

    groupnorm_kernel<<<BB * NGRP, 256>>>(x, ln1_w, ln1_b, xn);

    tgemm_kernel<0><<<dim3(3 * HH / GBN, MM / GBM), 256, gsmem>>>(
        xn, wattn, b_attn, nullptr, q, pk, pv, kr, vt, MM, 3 * HH, HH);

    flash_kernel<<<dim3(TT / 64, BB * NH), 128, fsmem>>>(q, kr, vt, a);

    tgemm_kernel<1><<<dim3(HH / GBN, MM / GBM), 256, gsmem>>>(
        a, waproj, b_aproj, x, x1, nullptr, nullptr, nullptr, nullptr, MM, HH, HH);

    groupnorm_kernel<<<BB * NGRP, 256>>>(x1, ln2_w, ln2_b, xn);

    tgemm_kernel<2><<<dim3(4 * HH / GBN, MM / GBM), 256, gsmem>>>(
        xn, wfc, b_fc, nullptr, h, nullptr, nullptr, nullptr, nullptr, MM, 4 * HH, HH);

    tgemm_kernel<1><<<dim3(HH / GBN, MM / GBM), 256, gsmem>>>(
        h, wmproj, b_mproj, x1, out_x, nullptr, nullptr, nullptr, nullptr, MM, HH, 4 * HH);
}

// round 7
// speedup vs baseline: 3.5192x; 1.0526x over previous
#include <cuda_runtime.h>
#include <cuda_bf16.h>
#include <math.h>

// Problem constants
#define BB   2
#define TT   2048
#define HH   1024
#define NH   16
#define HD   64
#define MM   (BB*TT)        // 4096
#define NGRP 32
#define GSZ  (HH/NGRP)      // 32
#define GELEM (TT*GSZ)      // 65536

// Scratch (device globals; no allocation allowed)
__device__ float g_xn[MM*HH];
__device__ float g_q [MM*HH];        // q, tf32-rounded, [b,h,t,d]
__device__ float g_kr[MM*HH];        // k, tf32-rounded, [b,h,t,d]
__device__ float g_vt[MM*HH];        // v^T, tf32-rounded, [b,h,d,t]
__device__ float g_a [MM*HH];
__device__ float g_x1[MM*HH];
__device__ float g_h [MM*4*HH];
__device__ float g_wattn [HH*3*HH];  // tf32-rounded weights
__device__ float g_waproj[HH*HH];
__device__ float g_wfc   [HH*4*HH];
__device__ float g_wmproj[4*HH*HH];
__device__ float g_part[512*2];      // groupnorm partial sums

__device__ __forceinline__ unsigned f2tf(float x) {
    unsigned u;
    asm("cvt.rna.tf32.f32 %0, %1;" : "=r"(u) : "f"(x));
    return u;
}
__device__ __forceinline__ float f2tff(float x) { return __uint_as_float(f2tf(x)); }

// ---------------------------------------------------------------------------
// Round weights to tf32
// ---------------------------------------------------------------------------
__global__ void round_tf32_kernel(const float* __restrict__ in,
                                  float* __restrict__ out, int n4)
{
    int i = blockIdx.x * blockDim.x + threadIdx.x;
    int stride = gridDim.x * blockDim.x;
    for (; i < n4; i += stride) {
        float4 v = ((const float4*)in)[i];
        v.x = f2tff(v.x); v.y = f2tff(v.y); v.z = f2tff(v.z); v.w = f2tff(v.w);
        ((float4*)out)[i] = v;
    }
}

// ---------------------------------------------------------------------------
// GroupNorm, split: stats (512 partial blocks) + apply (full-BW grid stride)
// ---------------------------------------------------------------------------
__global__ void gn_stats_kernel(const float* __restrict__ x,
                                float* __restrict__ part)
{
    int bg = blockIdx.x >> 3;          // 0..63  (batch*32+group)
    int slice = blockIdx.x & 7;        // 0..7
    int batch = bg >> 5, g = bg & 31;
    const float* xp = x + (size_t)batch * TT * HH + g * GSZ;
    int t = slice * 256 + threadIdx.x;                 // one row per thread
    const float4* row = (const float4*)(xp + (size_t)t * HH);
    float s = 0.f, ss = 0.f;
    #pragma unroll
    for (int i = 0; i < 8; i++) {
        float4 v = row[i];
        s  += v.x + v.y + v.z + v.w;
        ss += v.x*v.x + v.y*v.y + v.z*v.z + v.w*v.w;
    }
    // block reduce
    __shared__ float rs[256], rss[256];
    rs[threadIdx.x] = s; rss[threadIdx.x] = ss;
    __syncthreads();
    for (int o = 128; o > 0; o >>= 1) {
        if (threadIdx.x < o) {
            rs[threadIdx.x]  += rs[threadIdx.x + o];
            rss[threadIdx.x] += rss[threadIdx.x + o];
        }
        __syncthreads();
    }
    if (threadIdx.x == 0) {
        part[blockIdx.x * 2]     = rs[0];
        part[blockIdx.x * 2 + 1] = rss[0];
    }
}

__global__ void gn_apply_kernel(const float* __restrict__ x,
                                const float* __restrict__ part,
                                const float* __restrict__ w,
                                const float* __restrict__ b,
                                float* __restrict__ y)
{
    __shared__ float s_mean[64], s_rstd[64];
    if (threadIdx.x < 64) {
        float s = 0.f, ss = 0.f;
        #pragma unroll
        for (int i = 0; i < 8; i++) {
            s  += part[(threadIdx.x * 8 + i) * 2];
            ss += part[(threadIdx.x * 8 + i) * 2 + 1];
        }
        float mean = s * (1.0f / GELEM);
        float var  = ss * (1.0f / GELEM) - mean * mean;
        s_mean[threadIdx.x] = mean;
        s_rstd[threadIdx.x] = rsqrtf(var + 1e-5f);
    }
    __syncthreads();

    int n4 = MM * HH / 4;
    int i = blockIdx.x * blockDim.x + threadIdx.x;
    int stride = gridDim.x * blockDim.x;
    for (; i < n4; i += stride) {
        int e = i * 4;
        int ch = e & (HH - 1);
        int batch = e >> 21;              // e / (TT*HH); TT*HH = 2^21
        int bg = batch * 32 + (ch >> 5);
        float mean = s_mean[bg], rstd = s_rstd[bg];
        float4 v = ((const float4*)x)[i];
        v.x = f2tff((v.x - mean) * rstd * w[ch]   + b[ch]);
        v.y = f2tff((v.y - mean) * rstd * w[ch+1] + b[ch+1]);
        v.z = f2tff((v.z - mean) * rstd * w[ch+2] + b[ch+2]);
        v.w = f2tff((v.w - mean) * rstd * w[ch+3] + b[ch+3]);
        ((float4*)y)[i] = v;
    }
}

// ---------------------------------------------------------------------------
// TF32 tensor-core GEMM, cp.async 3-stage pipeline; operands pre-rounded.
// ---------------------------------------------------------------------------
#define GBM 128
#define GBN 128
#define GBK 32
#define APAD 36
#define BPAD 136
#define A_STG (GBM*APAD)
#define B_STG (GBK*BPAD)
#define STG   (A_STG + B_STG)          // 8960 floats / stage
#define NSTAGE 3

__device__ __forceinline__ float gelu_f(float v) {
    const float c = 0.7978845608028654f;
    float u = c * (v + 0.044715f * v * v * v);
    return 0.5f * v * (1.0f + tanhf(u));
}

__device__ __forceinline__ void mma_tf32(float* d, const unsigned* a, const unsigned* b) {
    asm volatile(
        "mma.sync.aligned.m16n8k8.row.col.f32.tf32.tf32.f32 "
        "{%0,%1,%2,%3}, {%4,%5,%6,%7}, {%8,%9}, {%0,%1,%2,%3};"
        : "+f"(d[0]), "+f"(d[1]), "+f"(d[2]), "+f"(d[3])
        : "r"(a[0]), "r"(a[1]), "r"(a[2]), "r"(a[3]),
          "r"(b[0]), "r"(b[1]));
}

__device__ __forceinline__ void cp16(float* dst, const float* src) {
    unsigned d = (unsigned)__cvta_generic_to_shared(dst);
    asm volatile("cp.async.cg.shared.global [%0], [%1], 16;" :: "r"(d), "l"(src));
}

template<int MODE>
__global__ void __launch_bounds__(256, 2)
tgemm_kernel(const float* __restrict__ A, const float* __restrict__ Bm,
             const float* __restrict__ bias, const float* __restrict__ res,
             float* __restrict__ C, float* __restrict__ C2, float* __restrict__ C3,
             float* __restrict__ KR, float* __restrict__ VT,
             int M, int N, int K)
{
    extern __shared__ float sh[];

    int tid  = threadIdx.x;
    int wid  = tid >> 5;
    int lane = tid & 31;
    int wm = wid >> 2;
    int wn = wid & 3;
    int lr = lane >> 2;
    int lc = lane & 3;

    int bm = blockIdx.y * GBM, bn = blockIdx.x * GBN;
    const float* Aptr = A + (size_t)bm * K;
    const float* Bptr = Bm + bn;

    float acc[4][4][4];
    #pragma unroll
    for (int i = 0; i < 4; i++)
        #pragma unroll
        for (int j = 0; j < 4; j++)
            #pragma unroll
            for (int e = 0; e < 4; e++) acc[i][j][e] = 0.f;

    int a_row = tid >> 3, a_off = (tid & 7) * 4;
    int ntiles = K / GBK;

    // prologue: load tiles 0, 1 into stages 0, 1 (one commit each)
    #pragma unroll
    for (int p = 0; p < 2; p++) {
        float* sA = sh + p * STG;
        float* sB = sA + A_STG;
        int k0 = p * GBK;
        #pragma unroll
        for (int r = 0; r < 4; r++) {
            int row = a_row + r * 32;
            cp16(&sA[row * APAD + a_off], Aptr + (size_t)row * K + k0 + a_off);
        }
        #pragma unroll
        for (int r = 0; r < 4; r++) {
            int c = tid + r * 256;
            int row = c >> 5, col = (c & 31) * 4;
            cp16(&sB[row * BPAD + col], Bptr + (size_t)(k0 + row) * N + col);
        }
        asm volatile("cp.async.commit_group;");
    }

    int stage = 0;        // stage holding tile `it`
    int lstage = 2;       // stage to load tile `it+2` into
    for (int it = 0; it < ntiles; it++) {
        // issue tile it+2 (stage lstage was freed by end-of-prev-iter barrier)
        if (it + 2 < ntiles) {
            int k0 = (it + 2) * GBK;
            float* sA = sh + lstage * STG;
            float* sB = sA + A_STG;
            #pragma unroll
            for (int r = 0; r < 4; r++) {
                int row = a_row + r * 32;
                cp16(&sA[row * APAD + a_off], Aptr + (size_t)row * K + k0 + a_off);
            }
            #pragma unroll
            for (int r = 0; r < 4; r++) {
                int c = tid + r * 256;
                int row = c >> 5, col = (c & 31) * 4;
                cp16(&sB[row * BPAD + col], Bptr + (size_t)(k0 + row) * N + col);
            }
        }
        asm volatile("cp.async.commit_group;");   // uniform commit (may be empty)
        asm volatile("cp.async.wait_group 2;");   // tile `it` complete
        __syncthreads();

        const float* As = sh + stage * STG;
        const float* Bs = As + A_STG;

        #pragma unroll
        for (int kk = 0; kk < GBK / 8; kk++) {
            int kb = kk * 8;
            unsigned af[4][4], bf[4][2];
            #pragma unroll
            for (int i = 0; i < 4; i++) {
                int m0 = wm * 64 + i * 16 + lr;
                af[i][0] = __float_as_uint(As[(size_t)m0 * APAD + kb + lc]);
                af[i][1] = __float_as_uint(As[(size_t)(m0 + 8) * APAD + kb + lc]);
                af[i][2] = __float_as_uint(As[(size_t)m0 * APAD + kb + lc + 4]);
                af[i][3] = __float_as_uint(As[(size_t)(m0 + 8) * APAD + kb + lc + 4]);
            }
            #pragma unroll
            for (int j = 0; j < 4; j++) {
                int n0 = wn * 32 + j * 8 + lr;
                bf[j][0] = __float_as_uint(Bs[(size_t)(kb + lc) * BPAD + n0]);
                bf[j][1] = __float_as_uint(Bs[(size_t)(kb + lc + 4) * BPAD + n0]);
            }
            #pragma unroll
            for (int i = 0; i < 4; i++)
                #pragma unroll
                for (int j = 0; j < 4; j++)
                    mma_tf32(acc[i][j], af[i], bf[j]);
        }
        __syncthreads();   // frees `stage` for the load issued at it+1

        stage = (stage + 1) % NSTAGE;
        lstage = (lstage + 1) % NSTAGE;
    }

    #pragma unroll
    for (int i = 0; i < 4; i++) {
        int rbase = bm + wm * 64 + i * 16 + lr;
        #pragma unroll
        for (int j = 0; j < 4; j++) {
            int cbase = bn + wn * 32 + j * 8 + 2 * lc;
            #pragma unroll
            for (int e = 0; e < 4; e++) {
                int m = rbase + (e >> 1) * 8;
                int n = cbase + (e & 1);
                float val = acc[i][j][e] + bias[n];
                if (MODE == 0) {
                    int bidx = m >> 11, t = m & 2047;
                    int part = n >> 10;
                    int nn = n & 1023;
                    int h = nn >> 6, d = nn & 63;
                    size_t idx = ((((size_t)bidx * NH + h) * TT) + t) * HD + d;
                    if (part == 0) {
                        C[idx] = f2tff(val);
                    } else if (part == 1) {
                        C2[idx] = val;
                        KR[idx] = f2tff(val);
                    } else {
                        C3[idx] = val;
                        size_t vt = (((size_t)bidx * NH + h) * HD + d) * TT + t;
                        VT[vt] = f2tff(val);
                    }
                } else if (MODE == 1) {
                    size_t idx = (size_t)m * N + n;
                    C[idx] = val + res[idx];
                } else {
                    C[(size_t)m * N + n] = f2tff(gelu_f(val));
                }
            }
        }
    }
}

// ---------------------------------------------------------------------------
// Flash attention, tf32 tensor cores, 2-stage K/V double buffer.
// ---------------------------------------------------------------------------
#define FP 68
#define FTILE (64*FP)

__global__ void __launch_bounds__(128, 2)
flash_kernel(const float* __restrict__ Q, const float* __restrict__ Kr,
             const float* __restrict__ Vt, float* __restrict__ Aout)
{
    extern __shared__ float sh[];
    // [Ks0 Vs0][Ks1 Vs1][Ps]
    float* Ps = sh + 4 * FTILE;

    int qb = blockIdx.x;
    int bh = blockIdx.y;
    int tid = threadIdx.x;
    int w   = tid >> 5;
    int lane = tid & 31;
    int lr = lane >> 2;
    int lc = lane & 3;

    const float* qbase  = Q  + ((size_t)bh * TT + (size_t)qb * 64 + w * 16) * HD;
    const float* kbase  = Kr + (size_t)bh * TT * HD;
    const float* vtbase = Vt + (size_t)bh * HD * TT;

    unsigned qf[8][4];
    #pragma unroll
    for (int kb = 0; kb < 8; kb++) {
        qf[kb][0] = __float_as_uint(qbase[(size_t)lr * HD + kb * 8 + lc]);
        qf[kb][1] = __float_as_uint(qbase[(size_t)(lr + 8) * HD + kb * 8 + lc]);
        qf[kb][2] = __float_as_uint(qbase[(size_t)lr * HD + kb * 8 + lc + 4]);
        qf[kb][3] = __float_as_uint(qbase[(size_t)(lr + 8) * HD + kb * 8 + lc + 4]);
    }

    float oacc[8][4];
    #pragma unroll
    for (int nb = 0; nb < 8; nb++)
        #pragma unroll
        for (int e = 0; e < 4; e++) oacc[nb][e] = 0.f;
    float m0 = -1e30f, m1 = -1e30f, l0 = 0.f, l1 = 0.f;

    // prologue: load tile 0 into stage 0
    {
        float* Ks = sh;
        float* Vs = sh + FTILE;
        #pragma unroll
        for (int i = 0; i < 8; i++) {
            int c = tid + i * 128;
            int rw = c >> 4, c4 = (c & 15) * 4;
            cp16(&Ks[rw * FP + c4], kbase + (size_t)rw * HD + c4);
            cp16(&Vs[rw * FP + c4], vtbase + (size_t)rw * TT + c4);
        }
        asm volatile("cp.async.commit_group;");
    }

    for (int kt = 0; kt <= qb; kt++) {
        // prefetch tile kt+1 into the other stage
        if (kt + 1 <= qb) {
            float* Ks = sh + ((kt + 1) & 1) * 2 * FTILE;
            float* Vs = Ks + FTILE;
            #pragma unroll
            for (int i = 0; i < 8; i++) {
                int c = tid + i * 128;
                int rw = c >> 4, c4 = (c & 15) * 4;
                cp16(&Ks[rw * FP + c4], kbase + ((size_t)(kt + 1) * 64 + rw) * HD + c4);
                cp16(&Vs[rw * FP + c4], vtbase + (size_t)rw * TT + (kt + 1) * 64 + c4);
            }
        }
        asm volatile("cp.async.commit_group;");
        asm volatile("cp.async.wait_group 1;");   // tile kt ready
        __syncthreads();

        const float* Ks = sh + (kt & 1) * 2 * FTILE;
        const float* Vs = Ks + FTILE;

        // S = Q @ K^T
        float sacc[8][4];
        #pragma unroll
        for (int nb = 0; nb < 8; nb++)
            #pragma unroll
            for (int e = 0; e < 4; e++) sacc[nb][e] = 0.f;

        #pragma unroll
        for (int kb = 0; kb < 8; kb++) {
            unsigned bf[8][2];
            #pragma unroll
            for (int nb = 0; nb < 8; nb++) {
                bf[nb][0] = __float_as_uint(Ks[(nb * 8 + lr) * FP + kb * 8 + lc]);
                bf[nb][1] = __float_as_uint(Ks[(nb * 8 + lr) * FP + kb * 8 + lc + 4]);
            }
            #pragma unroll
            for (int nb = 0; nb < 8; nb++)
                mma_tf32(sacc[nb], qf[kb], bf[nb]);
        }

        if (kt == qb) {
            int r0 = w * 16 + lr, r1 = r0 + 8;
            #pragma unroll
            for (int nb = 0; nb < 8; nb++) {
                int c0 = nb * 8 + 2 * lc, c1 = c0 + 1;
                if (c0 > r0) sacc[nb][0] = -1e30f;
                if (c1 > r0) sacc[nb][1] = -1e30f;
                if (c0 > r1) sacc[nb][2] = -1e30f;
                if (c1 > r1) sacc[nb][3] = -1e30f;
            }
        }

        float mx0 = -1e30f, mx1 = -1e30f;
        #pragma unroll
        for (int nb = 0; nb < 8; nb++) {
            mx0 = fmaxf(mx0, fmaxf(sacc[nb][0], sacc[nb][1]));
            mx1 = fmaxf(mx1, fmaxf(sacc[nb][2], sacc[nb][3]));
        }
        mx0 = fmaxf(mx0, __shfl_xor_sync(0xffffffffu, mx0, 1));
        mx0 = fmaxf(mx0, __shfl_xor_sync(0xffffffffu, mx0, 2));
        mx1 = fmaxf(mx1, __shfl_xor_sync(0xffffffffu, mx1, 1));
        mx1 = fmaxf(mx1, __shfl_xor_sync(0xffffffffu, mx1, 2));

        float mn0 = fmaxf(m0, mx0), mn1 = fmaxf(m1, mx1);
        float al0 = __expf(m0 - mn0), al1 = __expf(m1 - mn1);
        float sum0 = 0.f, sum1 = 0.f;
        #pragma unroll
        for (int nb = 0; nb < 8; nb++) {
            float p0 = __expf(sacc[nb][0] - mn0);
            float p1 = __expf(sacc[nb][1] - mn0);
            float p2 = __expf(sacc[nb][2] - mn1);
            float p3 = __expf(sacc[nb][3] - mn1);
            sum0 += p0 + p1; sum1 += p2 + p3;
            float2 v0 = make_float2(f2tff(p0), f2tff(p1));
            float2 v1 = make_float2(f2tff(p2), f2tff(p3));
            *(float2*)&Ps[(w * 16 + lr) * FP + nb * 8 + 2 * lc] = v0;
            *(float2*)&Ps[(w * 16 + lr + 8) * FP + nb * 8 + 2 * lc] = v1;
        }
        sum0 += __shfl_xor_sync(0xffffffffu, sum0, 1);
        sum0 += __shfl_xor_sync(0xffffffffu, sum0, 2);
        sum1 += __shfl_xor_sync(0xffffffffu, sum1, 1);
        sum1 += __shfl_xor_sync(0xffffffffu, sum1, 2);
        l0 = l0 * al0 + sum0; l1 = l1 * al1 + sum1;
        m0 = mn0; m1 = mn1;
        #pragma unroll
        for (int nb = 0; nb < 8; nb++) {
            oacc[nb][0] *= al0; oacc[nb][1] *= al0;
            oacc[nb][2] *= al1; oacc[nb][3] *= al1;
        }
        __syncwarp();   // Ps cross-lane visibility within warp

        // O += P @ V
        #pragma unroll
        for (int kb = 0; kb < 8; kb++) {
            unsigned af[4];
            af[0] = __float_as_uint(Ps[(w * 16 + lr) * FP + kb * 8 + lc]);
            af[1] = __float_as_uint(Ps[(w * 16 + lr + 8) * FP + kb * 8 + lc]);
            af[2] = __float_as_uint(Ps[(w * 16 + lr) * FP + kb * 8 + lc + 4]);
            af[3] = __float_as_uint(Ps[(w * 16 + lr + 8) * FP + kb * 8 + lc + 4]);
            #pragma unroll
            for (int nb = 0; nb < 8; nb++) {
                unsigned bf[2];
                bf[0] = __float_as_uint(Vs[(nb * 8 + lr) * FP + kb * 8 + lc]);
                bf[1] = __float_as_uint(Vs[(nb * 8 + lr) * FP + kb * 8 + lc + 4]);
                mma_tf32(oacc[nb], af, bf);
            }
        }
        __syncthreads();   // all warps done with stage kt&1 before next prefetch reuses it
    }

    int batch = bh >> 4, h = bh & 15;
    float inv0 = 1.0f / l0, inv1 = 1.0f / l1;
    int t0 = qb * 64 + w * 16 + lr;
    #pragma unroll
    for (int nb = 0; nb < 8; nb++) {
        int d0 = h * HD + nb * 8 + 2 * lc;
        float2 o0 = make_float2(f2tff(oacc[nb][0] * inv0), f2tff(oacc[nb][1] * inv0));
        float2 o1 = make_float2(f2tff(oacc[nb][2] * inv1), f2tff(oacc[nb][3] * inv1));
        *(float2*)(Aout + ((size_t)batch * TT + t0) * HH + d0) = o0;
        *(float2*)(Aout + ((size_t)batch * TT + t0 + 8) * HH + d0) = o1;
    }
}

// ---------------------------------------------------------------------------
// Launch
// ---------------------------------------------------------------------------
extern "C" void kernel_launch(void* const* d_in, const int* in_sizes, int n_in,
                              void* d_out, int out_size)
{
    const float* x       = (const float*)d_in[0];
    const float* w_attn  = (const float*)d_in[1];
    const float* b_attn  = (const float*)d_in[2];
    const float* w_aproj = (const float*)d_in[3];
    const float* b_aproj = (const float*)d_in[4];
    const float* ln1_w   = (const float*)d_in[5];
    const float* ln1_b   = (const float*)d_in[6];
    const float* ln2_w   = (const float*)d_in[7];
    const float* ln2_b   = (const float*)d_in[8];
    const float* w_fc    = (const float*)d_in[9];
    const float* b_fc    = (const float*)d_in[10];
    const float* w_mproj = (const float*)d_in[11];
    const float* b_mproj = (const float*)d_in[12];

    float* out_x = (float*)d_out;
    float* pk = out_x + (size_t)MM * HH;
    float* pv = pk + (size_t)MM * HH;

    float *xn, *q, *kr, *vt, *a, *x1, *h, *part;
    float *wattn, *waproj, *wfc, *wmproj;
    cudaGetSymbolAddress((void**)&xn, g_xn);
    cudaGetSymbolAddress((void**)&q,  g_q);
    cudaGetSymbolAddress((void**)&kr, g_kr);
    cudaGetSymbolAddress((void**)&vt, g_vt);
    cudaGetSymbolAddress((void**)&a,  g_a);
    cudaGetSymbolAddress((void**)&x1, g_x1);
    cudaGetSymbolAddress((void**)&h,  g_h);
    cudaGetSymbolAddress((void**)&part, g_part);
    cudaGetSymbolAddress((void**)&wattn,  g_wattn);
    cudaGetSymbolAddress((void**)&waproj, g_waproj);
    cudaGetSymbolAddress((void**)&wfc,    g_wfc);
    cudaGetSymbolAddress((void**)&wmproj, g_wmproj);

    size_t gsmem = NSTAGE * STG * sizeof(float);   // 107520 B
    cudaFuncSetAttribute(tgemm_kernel<0>, cudaFuncAttributeMaxDynamicSharedMemorySize, (int)gsmem);
    cudaFuncSetAttribute(tgemm_kernel<1>, cudaFuncAttributeMaxDynamicSharedMemorySize, (int)gsmem);
    cudaFuncSetAttribute(tgemm_kernel<2>, cudaFuncAttributeMaxDynamicSharedMemorySize, (int)gsmem);
    size_t fsmem = 5 * FTILE * sizeof(float);      // 87040 B
    cudaFuncSetAttribute(flash_kernel, cudaFuncAttributeMaxDynamicSharedMemorySize, (int)fsmem);

    round_tf32_kernel<<<1024, 256>>>(w_attn,  wattn,  HH * 3 * HH / 4);
    round_tf32_kernel<<<1024, 256>>>(w_aproj, waproj, HH * HH / 4);
    round_tf32_kernel<<<1024, 256>>>(w_fc,    wfc,    HH * 4 * HH / 4);
    round_tf32_kernel<<<1024, 256>>>(w_mproj, wmproj, 4 * HH * HH / 4);

    gn_stats_kernel<<<512, 256>>>(x, part);
    gn_apply_kernel<<<1024, 256>>>(x, part, ln1_w, ln1_b, xn);

    tgemm_kernel<0><<<dim3(3 * HH / GBN, MM / GBM), 256, gsmem>>>(
        xn, wattn, b_attn, nullptr, q, pk, pv, kr, vt, MM, 3 * HH, HH);

    flash_kernel<<<dim3(TT / 64, BB * NH), 128, fsmem>>>(q, kr, vt, a);

    tgemm_kernel<1><<<dim3(HH / GBN, MM / GBM), 256, gsmem>>>(
        a, waproj, b_aproj, x, x1, nullptr, nullptr, nullptr, nullptr, MM, HH, HH);

    gn_stats_kernel<<<512, 256>>>(x1, part);
    gn_apply_kernel<<<1024, 256>>>(x1, part, ln2_w, ln2_b, xn);

    tgemm_kernel<2><<<dim3(4 * HH / GBN, MM / GBM), 256, gsmem>>>(
        xn, wfc, b_fc, nullptr, h, nullptr, nullptr, nullptr, nullptr, MM, 4 * HH, HH);

    tgemm_kernel<1><<<dim3(HH / GBN, MM / GBM), 256, gsmem>>>(
        h, wmproj, b_mproj, x1, out_x, nullptr, nullptr, nullptr, nullptr, MM, HH, 4 * HH);
}

// round 8
// speedup vs baseline: 5.9794x; 1.6991x over previous
#include <cuda_runtime.h>
#include <cuda_fp16.h>
#include <math.h>

// Problem constants
#define BB   2
#define TT   2048
#define HH   1024
#define NH   16
#define HD   64
#define MM   (BB*TT)        // 4096
#define NGRP 32
#define GSZ  (HH/NGRP)      // 32
#define GELEM (TT*GSZ)      // 65536

// Scratch (device globals; no allocation allowed)
__device__ __half  g_xn[MM*HH];          // normalized activations (fp16)
__device__ __half  g_q [MM*HH];          // q  [b,h,t,d] fp16
__device__ __half  g_kr[MM*HH];          // k  [b,h,t,d] fp16
__device__ __half  g_vt[MM*HH];          // v^T [b,h,d,t] fp16
__device__ __half  g_a [MM*HH];          // attention out fp16
__device__ float   g_x1[MM*HH];          // residual stream (fp32, exact)
__device__ __half  g_h [MM*4*HH];        // MLP hidden fp16
__device__ __half2 g_wattn [(HH/2)*(3*HH)];   // k-pair-packed fp16 weights
__device__ __half2 g_waproj[(HH/2)*HH];
__device__ __half2 g_wfc   [(HH/2)*(4*HH)];
__device__ __half2 g_wmproj[(4*HH/2)*HH];
__device__ float   g_part[512*2];        // groupnorm partial sums

__device__ __forceinline__ unsigned pk2(float a, float b) {
    __half2 h = __floats2half2_rn(a, b);   // x(lo)=a, y(hi)=b
    return *(unsigned*)&h;
}

// ---------------------------------------------------------------------------
// Pack weights: fp32 [K][N] -> half2 [K/2][N], pair = (w[2k2][n], w[2k2+1][n])
// ---------------------------------------------------------------------------
__global__ void pack_w_kernel(const float* __restrict__ in,
                              __half2* __restrict__ out, int K, int N)
{
    int total = (K / 2) * (N / 4);
    int i = blockIdx.x * blockDim.x + threadIdx.x;
    int stride = gridDim.x * blockDim.x;
    int nq = N / 4;
    for (; i < total; i += stride) {
        int k2 = i / nq;
        int n  = (i - k2 * nq) * 4;
        float4 r0 = *(const float4*)(in + (size_t)(2 * k2) * N + n);
        float4 r1 = *(const float4*)(in + (size_t)(2 * k2 + 1) * N + n);
        uint4 u = make_uint4(pk2(r0.x, r1.x), pk2(r0.y, r1.y),
                             pk2(r0.z, r1.z), pk2(r0.w, r1.w));
        *(uint4*)(out + (size_t)k2 * N + n) = u;
    }
}

// ---------------------------------------------------------------------------
// GroupNorm: stats (512 partial blocks) + apply (fp16 out)
// ---------------------------------------------------------------------------
__global__ void gn_stats_kernel(const float* __restrict__ x,
                                float* __restrict__ part)
{
    int bg = blockIdx.x >> 3;
    int slice = blockIdx.x & 7;
    int batch = bg >> 5, g = bg & 31;
    const float* xp = x + (size_t)batch * TT * HH + g * GSZ;
    int t = slice * 256 + threadIdx.x;
    const float4* row = (const float4*)(xp + (size_t)t * HH);
    float s = 0.f, ss = 0.f;
    #pragma unroll
    for (int i = 0; i < 8; i++) {
        float4 v = row[i];
        s  += v.x + v.y + v.z + v.w;
        ss += v.x*v.x + v.y*v.y + v.z*v.z + v.w*v.w;
    }
    __shared__ float rs[256], rss[256];
    rs[threadIdx.x] = s; rss[threadIdx.x] = ss;
    __syncthreads();
    for (int o = 128; o > 0; o >>= 1) {
        if (threadIdx.x < o) {
            rs[threadIdx.x]  += rs[threadIdx.x + o];
            rss[threadIdx.x] += rss[threadIdx.x + o];
        }
        __syncthreads();
    }
    if (threadIdx.x == 0) {
        part[blockIdx.x * 2]     = rs[0];
        part[blockIdx.x * 2 + 1] = rss[0];
    }
}

__global__ void gn_apply_kernel(const float* __restrict__ x,
                                const float* __restrict__ part,
                                const float* __restrict__ w,
                                const float* __restrict__ b,
                                __half* __restrict__ y)
{
    __shared__ float s_mean[64], s_rstd[64];
    if (threadIdx.x < 64) {
        float s = 0.f, ss = 0.f;
        #pragma unroll
        for (int i = 0; i < 8; i++) {
            s  += part[(threadIdx.x * 8 + i) * 2];
            ss += part[(threadIdx.x * 8 + i) * 2 + 1];
        }
        float mean = s * (1.0f / GELEM);
        float var  = ss * (1.0f / GELEM) - mean * mean;
        s_mean[threadIdx.x] = mean;
        s_rstd[threadIdx.x] = rsqrtf(var + 1e-5f);
    }
    __syncthreads();

    int n4 = MM * HH / 4;
    int i = blockIdx.x * blockDim.x + threadIdx.x;
    int stride = gridDim.x * blockDim.x;
    for (; i < n4; i += stride) {
        int e = i * 4;
        int ch = e & (HH - 1);
        int batch = e >> 21;              // TT*HH = 2^21
        int bg = batch * 32 + (ch >> 5);
        float mean = s_mean[bg], rstd = s_rstd[bg];
        float4 v = ((const float4*)x)[i];
        uint2 o;
        o.x = pk2((v.x - mean) * rstd * w[ch]   + b[ch],
                  (v.y - mean) * rstd * w[ch+1] + b[ch+1]);
        o.y = pk2((v.z - mean) * rstd * w[ch+2] + b[ch+2],
                  (v.w - mean) * rstd * w[ch+3] + b[ch+3]);
        *(uint2*)(y + (size_t)i * 4) = o;
    }
}

// ---------------------------------------------------------------------------
// FP16 tensor-core GEMM (m16n8k16), cp.async 3-stage pipeline.
// BM=BN=128, BK=64, 256 threads, warp tile 64x32.
// A smem [m][k] half, row stride 72; B smem [k/2][n] half2, row stride 136.
// ---------------------------------------------------------------------------
#define GBM 128
#define GBN 128
#define GBK 64
#define APAD 72                         // halfs
#define BPAD 136                        // half2
#define A_BYTES (GBM*APAD*2)            // 18432
#define B_BYTES ((GBK/2)*BPAD*4)        // 17408
#define STG_BYTES (A_BYTES + B_BYTES)   // 35840
#define NSTAGE 3

__device__ __forceinline__ float gelu_f(float v) {
    const float c = 0.7978845608028654f;
    float u = c * (v + 0.044715f * v * v * v);
    return 0.5f * v * (1.0f + tanhf(u));
}

__device__ __forceinline__ void mma_f16(float* d, const unsigned* a, const unsigned* b) {
    asm volatile(
        "mma.sync.aligned.m16n8k16.row.col.f32.f16.f16.f32 "
        "{%0,%1,%2,%3}, {%4,%5,%6,%7}, {%8,%9}, {%0,%1,%2,%3};"
        : "+f"(d[0]), "+f"(d[1]), "+f"(d[2]), "+f"(d[3])
        : "r"(a[0]), "r"(a[1]), "r"(a[2]), "r"(a[3]),
          "r"(b[0]), "r"(b[1]));
}

__device__ __forceinline__ void cp16(void* dst, const void* src) {
    unsigned d = (unsigned)__cvta_generic_to_shared(dst);
    asm volatile("cp.async.cg.shared.global [%0], [%1], 16;" :: "r"(d), "l"(src));
}

template<int MODE>
__global__ void __launch_bounds__(256, 2)
tgemm_kernel(const __half* __restrict__ A, const __half2* __restrict__ Bp,
             const float* __restrict__ bias, const float* __restrict__ res,
             float* __restrict__ Cf, float* __restrict__ C2, float* __restrict__ C3,
             __half* __restrict__ Ch, __half* __restrict__ KR, __half* __restrict__ VT,
             int M, int N, int K)
{
    extern __shared__ char shraw[];

    int tid  = threadIdx.x;
    int wid  = tid >> 5;
    int lane = tid & 31;
    int wm = wid >> 2;
    int wn = wid & 3;
    int lr = lane >> 2;
    int lc = lane & 3;

    int bm = blockIdx.y * GBM, bn = blockIdx.x * GBN;
    const __half* Aptr = A + (size_t)bm * K;
    const __half2* Bptr = Bp + bn;

    float acc[4][4][4];
    #pragma unroll
    for (int i = 0; i < 4; i++)
        #pragma unroll
        for (int j = 0; j < 4; j++)
            #pragma unroll
            for (int e = 0; e < 4; e++) acc[i][j][e] = 0.f;

    int ntiles = K / GBK;

    // loader lambda-ish macro: A 1024 chunks (row=c>>3, ch=c&7), B 1024 (prow=c>>5, ch=c&31)
    #define LOAD_TILE(stg, k0)                                                        \
    {                                                                                 \
        __half*  sA = (__half*)(shraw + (stg) * STG_BYTES);                           \
        __half2* sB = (__half2*)(shraw + (stg) * STG_BYTES + A_BYTES);                \
        _Pragma("unroll")                                                             \
        for (int r = 0; r < 4; r++) {                                                 \
            int c = tid + r * 256;                                                    \
            int row = c >> 3, ch = (c & 7) * 8;                                       \
            cp16(sA + row * APAD + ch, Aptr + (size_t)row * K + (k0) + ch);           \
        }                                                                             \
        _Pragma("unroll")                                                             \
        for (int r = 0; r < 4; r++) {                                                 \
            int c = tid + r * 256;                                                    \
            int prow = c >> 5, ch = (c & 31) * 4;                                     \
            cp16(sB + prow * BPAD + ch, Bptr + (size_t)((k0)/2 + prow) * N + ch);     \
        }                                                                             \
    }

    // prologue: tiles 0,1 into stages 0,1
    LOAD_TILE(0, 0);
    asm volatile("cp.async.commit_group;");
    LOAD_TILE(1, GBK);
    asm volatile("cp.async.commit_group;");

    int stage = 0, lstage = 2;
    for (int it = 0; it < ntiles; it++) {
        if (it + 2 < ntiles) {
            LOAD_TILE(lstage, (it + 2) * GBK);
        }
        asm volatile("cp.async.commit_group;");
        asm volatile("cp.async.wait_group 2;");
        __syncthreads();

        const __half*  As = (const __half*)(shraw + stage * STG_BYTES);
        const __half2* Bs = (const __half2*)(shraw + stage * STG_BYTES + A_BYTES);

        #pragma unroll
        for (int kk = 0; kk < GBK / 16; kk++) {
            int kb = kk * 16;
            unsigned af[4][4], bf[4][2];
            #pragma unroll
            for (int i = 0; i < 4; i++) {
                int m0 = wm * 64 + i * 16 + lr;
                af[i][0] = *(const unsigned*)(As + (size_t)m0 * APAD + kb + 2*lc);
                af[i][1] = *(const unsigned*)(As + (size_t)(m0 + 8) * APAD + kb + 2*lc);
                af[i][2] = *(const unsigned*)(As + (size_t)m0 * APAD + kb + 2*lc + 8);
                af[i][3] = *(const unsigned*)(As + (size_t)(m0 + 8) * APAD + kb + 2*lc + 8);
            }
            #pragma unroll
            for (int j = 0; j < 4; j++) {
                int n0 = wn * 32 + j * 8 + lr;
                bf[j][0] = *(const unsigned*)(Bs + (size_t)(kk * 8 + lc) * BPAD + n0);
                bf[j][1] = *(const unsigned*)(Bs + (size_t)(kk * 8 + lc + 4) * BPAD + n0);
            }
            #pragma unroll
            for (int i = 0; i < 4; i++)
                #pragma unroll
                for (int j = 0; j < 4; j++)
                    mma_f16(acc[i][j], af[i], bf[j]);
        }
        __syncthreads();

        stage = (stage + 1) % NSTAGE;
        lstage = (lstage + 1) % NSTAGE;
    }
    #undef LOAD_TILE

    #pragma unroll
    for (int i = 0; i < 4; i++) {
        int rbase = bm + wm * 64 + i * 16 + lr;
        #pragma unroll
        for (int j = 0; j < 4; j++) {
            int cbase = bn + wn * 32 + j * 8 + 2 * lc;
            #pragma unroll
            for (int e = 0; e < 4; e++) {
                int m = rbase + (e >> 1) * 8;
                int n = cbase + (e & 1);
                float val = acc[i][j][e] + bias[n];
                if (MODE == 0) {
                    int bidx = m >> 11, t = m & 2047;
                    int part = n >> 10;
                    int nn = n & 1023;
                    int h = nn >> 6, d = nn & 63;
                    size_t idx = ((((size_t)bidx * NH + h) * TT) + t) * HD + d;
                    if (part == 0) {
                        Ch[idx] = __float2half_rn(val);
                    } else if (part == 1) {
                        C2[idx] = val;
                        KR[idx] = __float2half_rn(val);
                    } else {
                        C3[idx] = val;
                        size_t vt = (((size_t)bidx * NH + h) * HD + d) * TT + t;
                        VT[vt] = __float2half_rn(val);
                    }
                } else if (MODE == 1) {
                    size_t idx = (size_t)m * N + n;
                    Cf[idx] = val + res[idx];
                } else {
                    Ch[(size_t)m * N + n] = __float2half_rn(gelu_f(val));
                }
            }
        }
    }
}

// ---------------------------------------------------------------------------
// Flash attention, fp16 tensor cores, 2-stage K/V double buffer.
// ---------------------------------------------------------------------------
#define FPH 72                 // halfs per smem row
#define FTILEH (64*FPH)        // 4608 halfs = 9216 B per tile

__global__ void __launch_bounds__(128, 3)
flash_kernel(const __half* __restrict__ Q, const __half* __restrict__ Kr,
             const __half* __restrict__ Vt, __half* __restrict__ Aout)
{
    extern __shared__ char shraw[];
    __half* shh = (__half*)shraw;
    __half* Ps = shh + 4 * FTILEH;

    int qb = blockIdx.x;
    int bh = blockIdx.y;
    int tid = threadIdx.x;
    int w   = tid >> 5;
    int lane = tid & 31;
    int lr = lane >> 2;
    int lc = lane & 3;

    const __half* qbase  = Q  + ((size_t)bh * TT + (size_t)qb * 64 + w * 16) * HD;
    const __half* kbase  = Kr + (size_t)bh * TT * HD;
    const __half* vtbase = Vt + (size_t)bh * HD * TT;

    // Q fragments for 4 k16-steps
    unsigned qf[4][4];
    #pragma unroll
    for (int kk = 0; kk < 4; kk++) {
        int kb = kk * 16;
        qf[kk][0] = *(const unsigned*)(qbase + (size_t)lr * HD + kb + 2*lc);
        qf[kk][1] = *(const unsigned*)(qbase + (size_t)(lr + 8) * HD + kb + 2*lc);
        qf[kk][2] = *(const unsigned*)(qbase + (size_t)lr * HD + kb + 2*lc + 8);
        qf[kk][3] = *(const unsigned*)(qbase + (size_t)(lr + 8) * HD + kb + 2*lc + 8);
    }

    float oacc[8][4];
    #pragma unroll
    for (int nb = 0; nb < 8; nb++)
        #pragma unroll
        for (int e = 0; e < 4; e++) oacc[nb][e] = 0.f;
    float m0 = -1e30f, m1 = -1e30f, l0 = 0.f, l1 = 0.f;

    #define LOAD_KV(stg, kt0)                                                         \
    {                                                                                 \
        __half* Ks = shh + (stg) * 2 * FTILEH;                                        \
        __half* Vs = Ks + FTILEH;                                                     \
        _Pragma("unroll")                                                             \
        for (int i = 0; i < 4; i++) {                                                 \
            int c = tid + i * 128;                                                    \
            int row = c >> 3, ch = (c & 7) * 8;                                       \
            cp16(Ks + row * FPH + ch, kbase + ((size_t)(kt0) * 64 + row) * HD + ch);  \
            cp16(Vs + row * FPH + ch, vtbase + (size_t)row * TT + (kt0) * 64 + ch);   \
        }                                                                             \
    }

    LOAD_KV(0, 0);
    asm volatile("cp.async.commit_group;");

    for (int kt = 0; kt <= qb; kt++) {
        if (kt + 1 <= qb) {
            LOAD_KV((kt + 1) & 1, kt + 1);
        }
        asm volatile("cp.async.commit_group;");
        asm volatile("cp.async.wait_group 1;");
        __syncthreads();

        const __half* Ks = shh + (kt & 1) * 2 * FTILEH;
        const __half* Vs = Ks + FTILEH;

        // S = Q @ K^T
        float sacc[8][4];
        #pragma unroll
        for (int nb = 0; nb < 8; nb++)
            #pragma unroll
            for (int e = 0; e < 4; e++) sacc[nb][e] = 0.f;

        #pragma unroll
        for (int kk = 0; kk < 4; kk++) {
            int kb = kk * 16;
            unsigned bf[8][2];
            #pragma unroll
            for (int nb = 0; nb < 8; nb++) {
                bf[nb][0] = *(const unsigned*)(Ks + (size_t)(nb * 8 + lr) * FPH + kb + 2*lc);
                bf[nb][1] = *(const unsigned*)(Ks + (size_t)(nb * 8 + lr) * FPH + kb + 2*lc + 8);
            }
            #pragma unroll
            for (int nb = 0; nb < 8; nb++)
                mma_f16(sacc[nb], qf[kk], bf[nb]);
        }

        if (kt == qb) {
            int r0 = w * 16 + lr, r1 = r0 + 8;
            #pragma unroll
            for (int nb = 0; nb < 8; nb++) {
                int c0 = nb * 8 + 2 * lc, c1 = c0 + 1;
                if (c0 > r0) sacc[nb][0] = -1e30f;
                if (c1 > r0) sacc[nb][1] = -1e30f;
                if (c0 > r1) sacc[nb][2] = -1e30f;
                if (c1 > r1) sacc[nb][3] = -1e30f;
            }
        }

        float mx0 = -1e30f, mx1 = -1e30f;
        #pragma unroll
        for (int nb = 0; nb < 8; nb++) {
            mx0 = fmaxf(mx0, fmaxf(sacc[nb][0], sacc[nb][1]));
            mx1 = fmaxf(mx1, fmaxf(sacc[nb][2], sacc[nb][3]));
        }
        mx0 = fmaxf(mx0, __shfl_xor_sync(0xffffffffu, mx0, 1));
        mx0 = fmaxf(mx0, __shfl_xor_sync(0xffffffffu, mx0, 2));
        mx1 = fmaxf(mx1, __shfl_xor_sync(0xffffffffu, mx1, 1));
        mx1 = fmaxf(mx1, __shfl_xor_sync(0xffffffffu, mx1, 2));

        float mn0 = fmaxf(m0, mx0), mn1 = fmaxf(m1, mx1);
        float al0 = __expf(m0 - mn0), al1 = __expf(m1 - mn1);
        float sum0 = 0.f, sum1 = 0.f;
        #pragma unroll
        for (int nb = 0; nb < 8; nb++) {
            float p0 = __expf(sacc[nb][0] - mn0);
            float p1 = __expf(sacc[nb][1] - mn0);
            float p2 = __expf(sacc[nb][2] - mn1);
            float p3 = __expf(sacc[nb][3] - mn1);
            sum0 += p0 + p1; sum1 += p2 + p3;
            *(unsigned*)(Ps + (size_t)(w * 16 + lr) * FPH + nb * 8 + 2*lc)     = pk2(p0, p1);
            *(unsigned*)(Ps + (size_t)(w * 16 + lr + 8) * FPH + nb * 8 + 2*lc) = pk2(p2, p3);
        }
        sum0 += __shfl_xor_sync(0xffffffffu, sum0, 1);
        sum0 += __shfl_xor_sync(0xffffffffu, sum0, 2);
        sum1 += __shfl_xor_sync(0xffffffffu, sum1, 1);
        sum1 += __shfl_xor_sync(0xffffffffu, sum1, 2);
        l0 = l0 * al0 + sum0; l1 = l1 * al1 + sum1;
        m0 = mn0; m1 = mn1;
        #pragma unroll
        for (int nb = 0; nb < 8; nb++) {
            oacc[nb][0] *= al0; oacc[nb][1] *= al0;
            oacc[nb][2] *= al1; oacc[nb][3] *= al1;
        }
        __syncwarp();

        // O += P @ V
        #pragma unroll
        for (int kk = 0; kk < 4; kk++) {
            int kb = kk * 16;
            unsigned af[4];
            af[0] = *(const unsigned*)(Ps + (size_t)(w * 16 + lr) * FPH + kb + 2*lc);
            af[1] = *(const unsigned*)(Ps + (size_t)(w * 16 + lr + 8) * FPH + kb + 2*lc);
            af[2] = *(const unsigned*)(Ps + (size_t)(w * 16 + lr) * FPH + kb + 2*lc + 8);
            af[3] = *(const unsigned*)(Ps + (size_t)(w * 16 + lr + 8) * FPH + kb + 2*lc + 8);
            #pragma unroll
            for (int nb = 0; nb < 8; nb++) {
                unsigned bf[2];
                bf[0] = *(const unsigned*)(Vs + (size_t)(nb * 8 + lr) * FPH + kb + 2*lc);
                bf[1] = *(const unsigned*)(Vs + (size_t)(nb * 8 + lr) * FPH + kb + 2*lc + 8);
                mma_f16(oacc[nb], af, bf);
            }
        }
        __syncthreads();
    }
    #undef LOAD_KV

    int batch = bh >> 4, h = bh & 15;
    float inv0 = 1.0f / l0, inv1 = 1.0f / l1;
    int t0 = qb * 64 + w * 16 + lr;
    #pragma unroll
    for (int nb = 0; nb < 8; nb++) {
        int d0 = h * HD + nb * 8 + 2 * lc;
        *(unsigned*)(Aout + ((size_t)batch * TT + t0) * HH + d0)     = pk2(oacc[nb][0] * inv0, oacc[nb][1] * inv0);
        *(unsigned*)(Aout + ((size_t)batch * TT + t0 + 8) * HH + d0) = pk2(oacc[nb][2] * inv1, oacc[nb][3] * inv1);
    }
}

// ---------------------------------------------------------------------------
// Launch
// ---------------------------------------------------------------------------
extern "C" void kernel_launch(void* const* d_in, const int* in_sizes, int n_in,
                              void* d_out, int out_size)
{
    const float* x       = (const float*)d_in[0];
    const float* w_attn  = (const float*)d_in[1];
    const float* b_attn  = (const float*)d_in[2];
    const float* w_aproj = (const float*)d_in[3];
    const float* b_aproj = (const float*)d_in[4];
    const float* ln1_w   = (const float*)d_in[5];
    const float* ln1_b   = (const float*)d_in[6];
    const float* ln2_w   = (const float*)d_in[7];
    const float* ln2_b   = (const float*)d_in[8];
    const float* w_fc    = (const float*)d_in[9];
    const float* b_fc    = (const float*)d_in[10];
    const float* w_mproj = (const float*)d_in[11];
    const float* b_mproj = (const float*)d_in[12];

    float* out_x = (float*)d_out;
    float* pk = out_x + (size_t)MM * HH;
    float* pv = pk + (size_t)MM * HH;

    __half *xn, *q, *kr, *vt, *a, *h;
    float *x1, *part;
    __half2 *wattn, *waproj, *wfc, *wmproj;
    cudaGetSymbolAddress((void**)&xn, g_xn);
    cudaGetSymbolAddress((void**)&q,  g_q);
    cudaGetSymbolAddress((void**)&kr, g_kr);
    cudaGetSymbolAddress((void**)&vt, g_vt);
    cudaGetSymbolAddress((void**)&a,  g_a);
    cudaGetSymbolAddress((void**)&x1, g_x1);
    cudaGetSymbolAddress((void**)&h,  g_h);
    cudaGetSymbolAddress((void**)&part, g_part);
    cudaGetSymbolAddress((void**)&wattn,  g_wattn);
    cudaGetSymbolAddress((void**)&waproj, g_waproj);
    cudaGetSymbolAddress((void**)&wfc,    g_wfc);
    cudaGetSymbolAddress((void**)&wmproj, g_wmproj);

    size_t gsmem = NSTAGE * STG_BYTES;   // 107520 B
    cudaFuncSetAttribute(tgemm_kernel<0>, cudaFuncAttributeMaxDynamicSharedMemorySize, (int)gsmem);
    cudaFuncSetAttribute(tgemm_kernel<1>, cudaFuncAttributeMaxDynamicSharedMemorySize, (int)gsmem);
    cudaFuncSetAttribute(tgemm_kernel<2>, cudaFuncAttributeMaxDynamicSharedMemorySize, (int)gsmem);
    size_t fsmem = 5 * FTILEH * 2;       // 46080 B
    cudaFuncSetAttribute(flash_kernel, cudaFuncAttributeMaxDynamicSharedMemorySize, (int)fsmem);

    pack_w_kernel<<<1024, 256>>>(w_attn,  wattn,  HH, 3 * HH);
    pack_w_kernel<<<1024, 256>>>(w_aproj, waproj, HH, HH);
    pack_w_kernel<<<1024, 256>>>(w_fc,    wfc,    HH, 4 * HH);
    pack_w_kernel<<<1024, 256>>>(w_mproj, wmproj, 4 * HH, HH);

    gn_stats_kernel<<<512, 256>>>(x, part);
    gn_apply_kernel<<<1024, 256>>>(x, part, ln1_w, ln1_b, xn);

    tgemm_kernel<0><<<dim3(3 * HH / GBN, MM / GBM), 256, gsmem>>>(
        xn, wattn, b_attn, nullptr, nullptr, pk, pv, q, kr, vt, MM, 3 * HH, HH);

    flash_kernel<<<dim3(TT / 64, BB * NH), 128, fsmem>>>(q, kr, vt, a);

    tgemm_kernel<1><<<dim3(HH / GBN, MM / GBM), 256, gsmem>>>(
        a, waproj, b_aproj, x, x1, nullptr, nullptr, nullptr, nullptr, nullptr, MM, HH, HH);

    gn_stats_kernel<<<512, 256>>>(x1, part);
    gn_apply_kernel<<<1024, 256>>>(x1, part, ln2_w, ln2_b, xn);

    tgemm_kernel<2><<<dim3(4 * HH / GBN, MM / GBM), 256, gsmem>>>(
        xn, wfc, b_fc, nullptr, nullptr, nullptr, nullptr, h, nullptr, nullptr, MM, 4 * HH, HH);

    tgemm_kernel<1><<<dim3(HH / GBN, MM / GBM), 256, gsmem>>>(
        h, wmproj, b_mproj, x1, out_x, nullptr, nullptr, nullptr, nullptr, nullptr, MM, HH, 4 * HH);
}